// round 1
// baseline (speedup 1.0000x reference)
#include <cuda_runtime.h>
#include <math.h>

// ---- model dims ----
#define SQ   2048
#define HID  1024
#define NHEAD 16
#define HD   64
#define FFD  4096
#define NEXP 8
#define TOPK 2
#define VOC  32000
#define NLAY 2

// ---- scratch (device globals; no mallocs allowed) ----
__device__ float g_x   [SQ * HID];            // residual stream
__device__ float g_ln  [SQ * HID];            // layernorm output
__device__ float g_qkv [SQ * 3 * HID];        // qkv projections
__device__ float g_attn[SQ * HID];            // attention context (pre-Wo)
__device__ float g_hid [SQ * TOPK * FFD];     // MoE hidden, indexed by slot
__device__ float g_out2[SQ * TOPK * HID];     // MoE expert out, indexed by slot
__device__ float g_slotw[SQ * TOPK];          // top-k weights per slot
__device__ int   g_elist[NEXP * SQ];          // per-expert slot lists
__device__ int   g_ecnt [NEXP];               // per-expert counts

// ---------------------------------------------------------------------------
__global__ void embed_k(const int* __restrict__ idx,
                        const float* __restrict__ tok,
                        const float* __restrict__ pos) {
    int s = blockIdx.x;
    int row = idx[s];
    for (int h = threadIdx.x; h < HID; h += blockDim.x)
        g_x[s * HID + h] = tok[(long)row * HID + h] + pos[(long)s * HID + h];
}

// ---------------------------------------------------------------------------
__global__ void ln_k(const float* __restrict__ in, float* __restrict__ out,
                     const float* __restrict__ g, const float* __restrict__ b) {
    int s = blockIdx.x, t = threadIdx.x;
    __shared__ float red[256];
    const float* row = in + (long)s * HID;

    float sum = 0.f;
    for (int h = t; h < HID; h += 256) sum += row[h];
    red[t] = sum; __syncthreads();
    for (int o = 128; o > 0; o >>= 1) { if (t < o) red[t] += red[t + o]; __syncthreads(); }
    float mu = red[0] * (1.0f / HID);
    __syncthreads();

    float vs = 0.f;
    for (int h = t; h < HID; h += 256) { float d = row[h] - mu; vs += d * d; }
    red[t] = vs; __syncthreads();
    for (int o = 128; o > 0; o >>= 1) { if (t < o) red[t] += red[t + o]; __syncthreads(); }
    float inv = rsqrtf(red[0] * (1.0f / HID) + 1e-5f);

    float* orow = out + (long)s * HID;
    for (int h = t; h < HID; h += 256)
        orow[h] = (row[h] - mu) * inv * g[h] + b[h];
}

// ---------------------------------------------------------------------------
// Generic tiled SGEMM. 64x64 tile, BK=16, 256 threads, 4x4 microtile.
// row_mode: 0 = direct rows (M x N)
//           1 = MoE gemm1: A row = list[i]/TOPK (token), C row = list[i] (slot)
//           2 = MoE gemm2: A row = list[i] (slot), C row = list[i] (slot)
__global__ void sgemm_k(const float* __restrict__ A, int lda,
                        const float* __restrict__ Bmat, int ldb, int transB,
                        long strideB,
                        const float* __restrict__ bias,
                        float* __restrict__ C, int ldc,
                        int M, int N, int K,
                        int accum, int gelu,
                        int row_mode,
                        const int* __restrict__ elist,
                        const int* __restrict__ ecnt) {
    int e = blockIdx.z;
    const float* B = Bmat + (long)e * strideB;
    int Me = M;
    const int* list = nullptr;
    if (row_mode) { Me = ecnt[e]; list = elist + e * SQ; }
    int m0 = blockIdx.y * 64;
    if (m0 >= Me) return;
    int n0 = blockIdx.x * 64;

    __shared__ float As[16][64];
    __shared__ float Bs[16][64];

    int t  = threadIdx.x;
    int tx = t & 15, ty = t >> 4;

    // A-load mapping: 64 rows x 16 k, float4 along k
    int am = t >> 2, ak = (t & 3) * 4;
    int lrow = m0 + am;
    long arow = -1;
    if (lrow < Me) {
        if (row_mode == 0) arow = lrow;
        else { int slot = list[lrow]; arow = (row_mode == 1) ? (slot / TOPK) : slot; }
    }

    // B-load mapping
    int bn, bk;
    if (!transB) { bk = t >> 4; bn = (t & 15) * 4; }
    else         { bn = t >> 2; bk = (t & 3) * 4;  }

    float acc[4][4];
    #pragma unroll
    for (int i = 0; i < 4; i++)
        #pragma unroll
        for (int j = 0; j < 4; j++) acc[i][j] = 0.f;

    for (int k0 = 0; k0 < K; k0 += 16) {
        float4 av = make_float4(0.f, 0.f, 0.f, 0.f);
        if (arow >= 0) av = *(const float4*)&A[arow * (long)lda + k0 + ak];
        As[ak + 0][am] = av.x; As[ak + 1][am] = av.y;
        As[ak + 2][am] = av.z; As[ak + 3][am] = av.w;

        if (!transB) {
            float4 bv = *(const float4*)&B[(long)(k0 + bk) * ldb + n0 + bn];
            *(float4*)&Bs[bk][bn] = bv;
        } else {
            float4 bv = *(const float4*)&B[(long)(n0 + bn) * ldb + k0 + bk];
            Bs[bk + 0][bn] = bv.x; Bs[bk + 1][bn] = bv.y;
            Bs[bk + 2][bn] = bv.z; Bs[bk + 3][bn] = bv.w;
        }
        __syncthreads();

        #pragma unroll
        for (int kk = 0; kk < 16; kk++) {
            float4 a = *(float4*)&As[kk][ty * 4];
            float4 b = *(float4*)&Bs[kk][tx * 4];
            acc[0][0] += a.x * b.x; acc[0][1] += a.x * b.y; acc[0][2] += a.x * b.z; acc[0][3] += a.x * b.w;
            acc[1][0] += a.y * b.x; acc[1][1] += a.y * b.y; acc[1][2] += a.y * b.z; acc[1][3] += a.y * b.w;
            acc[2][0] += a.z * b.x; acc[2][1] += a.z * b.y; acc[2][2] += a.z * b.z; acc[2][3] += a.z * b.w;
            acc[3][0] += a.w * b.x; acc[3][1] += a.w * b.y; acc[3][2] += a.w * b.z; acc[3][3] += a.w * b.w;
        }
        __syncthreads();
    }

    #pragma unroll
    for (int i = 0; i < 4; i++) {
        int lr = m0 + ty * 4 + i;
        if (lr >= Me) continue;
        long crow = (row_mode == 0) ? (long)lr : (long)list[lr];
        #pragma unroll
        for (int j = 0; j < 4; j++) {
            int n = n0 + tx * 4 + j;
            float v = acc[i][j];
            if (bias)  v += bias[n];
            if (gelu)  v = v * normcdff(v);   // exact GELU: x * Phi(x)
            long ci = crow * (long)ldc + n;
            if (accum) C[ci] += v; else C[ci] = v;
        }
    }
}

// ---------------------------------------------------------------------------
// Causal flash attention. Block = 128 threads = 64 queries x 2 half-threads.
// grid = (SQ/64, NHEAD). Reads g_qkv, writes g_attn (head-concat layout).
__global__ void attn_k() {
    int h  = blockIdx.y;
    int q0 = blockIdx.x * 64;
    int t  = threadIdx.x;
    int ql = t >> 1, half = t & 1;
    int q  = q0 + ql;

    float qv[32];
    #pragma unroll
    for (int d = 0; d < 32; d++)
        qv[d] = g_qkv[(long)q * 3072 + h * 64 + half * 32 + d];

    float m = -1e30f, l = 0.f;
    float acc[32];
    #pragma unroll
    for (int d = 0; d < 32; d++) acc[d] = 0.f;

    __shared__ float Ks[64][64];
    __shared__ float Vs[64][64];

    for (int kt = 0; kt <= q0 + 63; kt += 64) {
        for (int i = t * 4; i < 64 * 64; i += 128 * 4) {
            int kk = i >> 6, d = i & 63;
            *(float4*)&Ks[kk][d] = *(const float4*)&g_qkv[(long)(kt + kk) * 3072 + 1024 + h * 64 + d];
            *(float4*)&Vs[kk][d] = *(const float4*)&g_qkv[(long)(kt + kk) * 3072 + 2048 + h * 64 + d];
        }
        __syncthreads();

        int kmax = q - kt + 1;               // #valid keys this tile for this q
        if (kmax > 64) kmax = 64;
        for (int kk = 0; kk < 64; kk++) {
            float p = 0.f;
            #pragma unroll
            for (int d = 0; d < 32; d++) p += qv[d] * Ks[kk][half * 32 + d];
            p += __shfl_xor_sync(0xffffffffu, p, 1);
            if (kk < kmax) {
                float s  = p * 0.125f;       // 1/sqrt(64)
                float mn = fmaxf(m, s);
                float cor = expf(m - mn);
                float pe  = expf(s - mn);
                l = l * cor + pe;
                #pragma unroll
                for (int d = 0; d < 32; d++)
                    acc[d] = acc[d] * cor + pe * Vs[kk][half * 32 + d];
                m = mn;
            }
        }
        __syncthreads();
    }

    float inv = 1.f / l;
    #pragma unroll
    for (int d = 0; d < 32; d++)
        g_attn[(long)q * HID + h * 64 + half * 32 + d] = acc[d] * inv;
}

// ---------------------------------------------------------------------------
__global__ void zero_cnt_k() { if (threadIdx.x < NEXP) g_ecnt[threadIdx.x] = 0; }

// Router: logits -> softmax(8) -> top-2 (jax tie order: lowest index first)
// -> slot weights + per-expert slot lists (atomic positions; output keyed by
// slot so final result is deterministic regardless of list order).
__global__ void router_k(const float* __restrict__ rw) {
    int tok = blockIdx.x, t = threadIdx.x;   // 128 threads
    __shared__ float sm[NEXP][128];
    __shared__ float logits[NEXP];
    const float* xr = g_ln + (long)tok * HID;

    for (int e = 0; e < NEXP; e++) {
        float s = 0.f;
        for (int j = t; j < HID; j += 128) s += xr[j] * rw[e * HID + j];
        sm[e][t] = s;
    }
    __syncthreads();
    if (t < NEXP) {
        float s = 0.f;
        for (int j = 0; j < 128; j++) s += sm[t][j];
        logits[t] = s;
    }
    __syncthreads();
    if (t == 0) {
        float mx = logits[0];
        for (int e = 1; e < NEXP; e++) mx = fmaxf(mx, logits[e]);
        float p[NEXP], den = 0.f;
        for (int e = 0; e < NEXP; e++) { p[e] = expf(logits[e] - mx); den += p[e]; }
        float idn = 1.f / den;
        for (int e = 0; e < NEXP; e++) p[e] *= idn;
        int i1 = 0;
        for (int e = 1; e < NEXP; e++) if (p[e] > p[i1]) i1 = e;
        int i2 = -1;
        for (int e = 0; e < NEXP; e++) {
            if (e == i1) continue;
            if (i2 < 0 || p[e] > p[i2]) i2 = e;
        }
        g_slotw[tok * 2 + 0] = p[i1];
        g_slotw[tok * 2 + 1] = p[i2];
        int p1 = atomicAdd(&g_ecnt[i1], 1); g_elist[i1 * SQ + p1] = tok * 2 + 0;
        int p2 = atomicAdd(&g_ecnt[i2], 1); g_elist[i2 * SQ + p2] = tok * 2 + 1;
    }
}

// ---------------------------------------------------------------------------
__global__ void combine_k() {
    int tok = blockIdx.x;
    float w0 = g_slotw[tok * 2 + 0];
    float w1 = g_slotw[tok * 2 + 1];
    const float* o0 = g_out2 + (long)(tok * 2 + 0) * HID;
    const float* o1 = g_out2 + (long)(tok * 2 + 1) * HID;
    float* xr = g_x + (long)tok * HID;
    for (int h = threadIdx.x; h < HID; h += blockDim.x)
        xr[h] += w0 * o0[h] + w1 * o1[h];
}

// ---------------------------------------------------------------------------
extern "C" void kernel_launch(void* const* d_in, const int* in_sizes, int n_in,
                              void* d_out, int out_size) {
    const int*   idx  = (const int*)  d_in[0];
    const float* tok  = (const float*)d_in[1];
    const float* pos  = (const float*)d_in[2];
    const float* ln1g = (const float*)d_in[3];
    const float* ln1b = (const float*)d_in[4];
    const float* wqkv = (const float*)d_in[5];
    const float* bqkv = (const float*)d_in[6];
    const float* wo   = (const float*)d_in[7];
    const float* bo   = (const float*)d_in[8];
    const float* ln2g = (const float*)d_in[9];
    const float* ln2b = (const float*)d_in[10];
    const float* rw   = (const float*)d_in[11];
    const float* w1   = (const float*)d_in[12];
    const float* w2   = (const float*)d_in[13];
    const float* lnfg = (const float*)d_in[14];
    const float* lnfb = (const float*)d_in[15];
    float* out = (float*)d_out;

    void *px_, *pln_, *pqkv_, *pattn_, *phid_, *pout2_, *pel_, *pec_;
    cudaGetSymbolAddress(&px_,    g_x);
    cudaGetSymbolAddress(&pln_,   g_ln);
    cudaGetSymbolAddress(&pqkv_,  g_qkv);
    cudaGetSymbolAddress(&pattn_, g_attn);
    cudaGetSymbolAddress(&phid_,  g_hid);
    cudaGetSymbolAddress(&pout2_, g_out2);
    cudaGetSymbolAddress(&pel_,   g_elist);
    cudaGetSymbolAddress(&pec_,   g_ecnt);
    float* px    = (float*)px_;
    float* pln   = (float*)pln_;
    float* pqkv  = (float*)pqkv_;
    float* pattn = (float*)pattn_;
    float* phid  = (float*)phid_;
    float* pout2 = (float*)pout2_;
    const int* pel = (const int*)pel_;
    const int* pec = (const int*)pec_;

    embed_k<<<SQ, 256>>>(idx, tok, pos);

    for (int l = 0; l < NLAY; l++) {
        // x_ln = LN1(x)
        ln_k<<<SQ, 256>>>(px, pln, ln1g + l * HID, ln1b + l * HID);
        // qkv = x_ln @ wqkv.T + bqkv   (M=2048, N=3072, K=1024)
        sgemm_k<<<dim3(48, 32, 1), 256>>>(
            pln, HID,
            wqkv + (long)l * 3 * HID * HID, HID, /*transB=*/1, 0,
            bqkv + (long)l * 3 * HID,
            pqkv, 3 * HID,
            SQ, 3 * HID, HID,
            0, 0, 0, nullptr, nullptr);
        // flash attention
        attn_k<<<dim3(SQ / 64, NHEAD), 128>>>();
        // x += attn @ wo.T + bo   (M=2048, N=1024, K=1024, residual accumulate)
        sgemm_k<<<dim3(16, 32, 1), 256>>>(
            pattn, HID,
            wo + (long)l * HID * HID, HID, /*transB=*/1, 0,
            bo + (long)l * HID,
            px, HID,
            SQ, HID, HID,
            /*accum=*/1, 0, 0, nullptr, nullptr);
        // x_ln = LN2(x)
        ln_k<<<SQ, 256>>>(px, pln, ln2g + l * HID, ln2b + l * HID);
        // router + top-2 dispatch
        zero_cnt_k<<<1, 32>>>();
        router_k<<<SQ, 128>>>(rw + (long)l * NEXP * HID);
        // hid[slot] = gelu(x_ln[token] @ w1[e])   (per-expert gathered rows)
        sgemm_k<<<dim3(FFD / 64, SQ / 64, NEXP), 256>>>(
            pln, HID,
            w1 + (long)l * NEXP * HID * FFD, FFD, /*transB=*/0, (long)HID * FFD,
            nullptr,
            phid, FFD,
            SQ, FFD, HID,
            0, /*gelu=*/1, /*row_mode=*/1, pel, pec);
        // out2[slot] = hid[slot] @ w2[e]
        sgemm_k<<<dim3(HID / 64, SQ / 64, NEXP), 256>>>(
            phid, FFD,
            w2 + (long)l * NEXP * FFD * HID, HID, /*transB=*/0, (long)FFD * HID,
            nullptr,
            pout2, HID,
            SQ, HID, FFD,
            0, 0, /*row_mode=*/2, pel, pec);
        // x += w0*out2[2t] + w1*out2[2t+1]
        combine_k<<<SQ, 256>>>();
    }

    // final LN + tied lm_head: logits = LN(x) @ tok_emb.T  (M=2048, N=32000, K=1024)
    ln_k<<<SQ, 256>>>(px, pln, lnfg, lnfb);
    sgemm_k<<<dim3(VOC / 64, SQ / 64, 1), 256>>>(
        pln, HID,
        tok, HID, /*transB=*/1, 0,
        nullptr,
        out, VOC,
        SQ, VOC, HID,
        0, 0, 0, nullptr, nullptr);
}

// round 2
// speedup vs baseline: 1.1326x; 1.1326x over previous
#include <cuda_runtime.h>
#include <math.h>

// ---- model dims ----
#define SQ   2048
#define HID  1024
#define NHEAD 16
#define HD   64
#define FFD  4096
#define NEXP 8
#define TOPK 2
#define VOC  32000
#define NLAY 2

typedef unsigned long long u64;

__device__ __forceinline__ u64 pk2(float lo, float hi) {
    u64 r; asm("mov.b64 %0, {%1,%2};" : "=l"(r) : "f"(lo), "f"(hi)); return r;
}
__device__ __forceinline__ void upk2(u64 v, float& lo, float& hi) {
    asm("mov.b64 {%0,%1}, %2;" : "=f"(lo), "=f"(hi) : "l"(v));
}
__device__ __forceinline__ u64 ffma2(u64 a, u64 b, u64 c) {
    u64 d; asm("fma.rn.f32x2 %0, %1, %2, %3;" : "=l"(d) : "l"(a), "l"(b), "l"(c)); return d;
}
__device__ __forceinline__ u64 fmul2(u64 a, u64 b) {
    u64 d; asm("mul.rn.f32x2 %0, %1, %2;" : "=l"(d) : "l"(a), "l"(b)); return d;
}

// ---- scratch (device globals; no mallocs allowed) ----
__device__ float g_x   [SQ * HID];
__device__ float g_ln  [SQ * HID];
__device__ float g_qkv [SQ * 3 * HID];
__device__ float g_attn[SQ * HID];
__device__ float g_hid [SQ * TOPK * FFD];
__device__ float g_out2[SQ * TOPK * HID];
__device__ float g_slotw[SQ * TOPK];
__device__ int   g_elist[NEXP * SQ];
__device__ int   g_ecnt [NEXP];

// ---------------------------------------------------------------------------
__global__ void embed_k(const int* __restrict__ idx,
                        const float* __restrict__ tok,
                        const float* __restrict__ pos) {
    int s = blockIdx.x;
    int row = idx[s];
    for (int h = threadIdx.x; h < HID; h += blockDim.x)
        g_x[s * HID + h] = tok[(long)row * HID + h] + pos[(long)s * HID + h];
}

// ---------------------------------------------------------------------------
__global__ void ln_k(const float* __restrict__ in, float* __restrict__ out,
                     const float* __restrict__ g, const float* __restrict__ b) {
    int s = blockIdx.x, t = threadIdx.x;
    __shared__ float red[256];
    const float* row = in + (long)s * HID;

    float sum = 0.f;
    for (int h = t; h < HID; h += 256) sum += row[h];
    red[t] = sum; __syncthreads();
    for (int o = 128; o > 0; o >>= 1) { if (t < o) red[t] += red[t + o]; __syncthreads(); }
    float mu = red[0] * (1.0f / HID);
    __syncthreads();

    float vs = 0.f;
    for (int h = t; h < HID; h += 256) { float d = row[h] - mu; vs += d * d; }
    red[t] = vs; __syncthreads();
    for (int o = 128; o > 0; o >>= 1) { if (t < o) red[t] += red[t + o]; __syncthreads(); }
    float inv = rsqrtf(red[0] * (1.0f / HID) + 1e-5f);

    float* orow = out + (long)s * HID;
    for (int h = t; h < HID; h += 256)
        orow[h] = (row[h] - mu) * inv * g[h] + b[h];
}

// ---------------------------------------------------------------------------
// SGEMM v2: 128x128 tile, BK=16, 256 threads, double-buffered, f32x2 inner.
// row_mode: 0 direct; 1 MoE gemm1 (A row = slot/2, C row = slot);
//           2 MoE gemm2 (A row = slot, C row = slot).
__global__ void __launch_bounds__(256) sgemm_k(
        const float* __restrict__ A, int lda,
        const float* __restrict__ Bmat, int ldb, int transB, long strideB,
        const float* __restrict__ bias,
        float* __restrict__ C, int ldc,
        int M, int N, int K,
        int accum, int gelu, int row_mode,
        const int* __restrict__ elist, const int* __restrict__ ecnt) {
    int e = blockIdx.z;
    const float* B = Bmat + (long)e * strideB;
    int Me = M;
    const int* list = nullptr;
    if (row_mode) { Me = ecnt[e]; list = elist + e * SQ; }
    int m0 = blockIdx.y * 128;
    if (m0 >= Me) return;
    int n0 = blockIdx.x * 128;

    __shared__ float As[2][16][132];
    __shared__ float Bs[2][16][132];

    int t  = threadIdx.x;
    int tx = t & 15, ty = t >> 4;

    // A loader mapping: each thread loads 8 consecutive k for one row
    int am = t & 127, ak = (t >> 7) * 8;
    int lrow = m0 + am;
    const float* Aptr = nullptr;
    if (lrow < Me) {
        long arow;
        if (row_mode == 0) arow = lrow;
        else { int slot = list[lrow]; arow = (row_mode == 1) ? (slot / TOPK) : slot; }
        Aptr = A + arow * (long)lda;
    }

    // B loader mappings
    int bk_nt = t >> 4, bn_nt = (t & 15) * 8;   // non-trans: row k, 8 n
    int bn_t  = t & 127, bk_t  = (t >> 7) * 8;  // trans: row n, 8 k

    u64 acc[4][8];
    #pragma unroll
    for (int i = 0; i < 4; i++)
        #pragma unroll
        for (int j = 0; j < 8; j++) acc[i][j] = 0ULL;

    float4 ra0, ra1, rb0, rb1;
    const float4 z4 = make_float4(0.f, 0.f, 0.f, 0.f);

    // ---- load k0=0 to regs ----
    {
        int k0 = 0;
        ra0 = Aptr ? *(const float4*)&Aptr[k0 + ak]     : z4;
        ra1 = Aptr ? *(const float4*)&Aptr[k0 + ak + 4] : z4;
        if (!transB) {
            rb0 = *(const float4*)&B[(long)(k0 + bk_nt) * ldb + n0 + bn_nt];
            rb1 = *(const float4*)&B[(long)(k0 + bk_nt) * ldb + n0 + bn_nt + 4];
        } else {
            rb0 = *(const float4*)&B[(long)(n0 + bn_t) * ldb + k0 + bk_t];
            rb1 = *(const float4*)&B[(long)(n0 + bn_t) * ldb + k0 + bk_t + 4];
        }
    }
    // store to buf 0
    {
        As[0][ak + 0][am] = ra0.x; As[0][ak + 1][am] = ra0.y;
        As[0][ak + 2][am] = ra0.z; As[0][ak + 3][am] = ra0.w;
        As[0][ak + 4][am] = ra1.x; As[0][ak + 5][am] = ra1.y;
        As[0][ak + 6][am] = ra1.z; As[0][ak + 7][am] = ra1.w;
        if (!transB) {
            *(float4*)&Bs[0][bk_nt][bn_nt]     = rb0;
            *(float4*)&Bs[0][bk_nt][bn_nt + 4] = rb1;
        } else {
            Bs[0][bk_t + 0][bn_t] = rb0.x; Bs[0][bk_t + 1][bn_t] = rb0.y;
            Bs[0][bk_t + 2][bn_t] = rb0.z; Bs[0][bk_t + 3][bn_t] = rb0.w;
            Bs[0][bk_t + 4][bn_t] = rb1.x; Bs[0][bk_t + 5][bn_t] = rb1.y;
            Bs[0][bk_t + 6][bn_t] = rb1.z; Bs[0][bk_t + 7][bn_t] = rb1.w;
        }
    }
    __syncthreads();

    int buf = 0;
    for (int k0 = 0; k0 < K; k0 += 16) {
        int has_next = (k0 + 16 < K);
        if (has_next) {
            int kn = k0 + 16;
            ra0 = Aptr ? *(const float4*)&Aptr[kn + ak]     : z4;
            ra1 = Aptr ? *(const float4*)&Aptr[kn + ak + 4] : z4;
            if (!transB) {
                rb0 = *(const float4*)&B[(long)(kn + bk_nt) * ldb + n0 + bn_nt];
                rb1 = *(const float4*)&B[(long)(kn + bk_nt) * ldb + n0 + bn_nt + 4];
            } else {
                rb0 = *(const float4*)&B[(long)(n0 + bn_t) * ldb + kn + bk_t];
                rb1 = *(const float4*)&B[(long)(n0 + bn_t) * ldb + kn + bk_t + 4];
            }
        }

        const float (*pA)[132] = As[buf];
        const float (*pB)[132] = Bs[buf];
        #pragma unroll
        for (int kk = 0; kk < 16; kk++) {
            // A fragment: 8 consecutive m-rows => 4 native u64 pairs
            ulonglong2 av0 = *(const ulonglong2*)&pA[kk][ty * 8];
            ulonglong2 av1 = *(const ulonglong2*)&pA[kk][ty * 8 + 4];
            u64 a2[4] = { av0.x, av0.y, av1.x, av1.y };
            float4 bf0 = *(const float4*)&pB[kk][tx * 8];
            float4 bf1 = *(const float4*)&pB[kk][tx * 8 + 4];
            u64 bb[8];
            bb[0] = pk2(bf0.x, bf0.x); bb[1] = pk2(bf0.y, bf0.y);
            bb[2] = pk2(bf0.z, bf0.z); bb[3] = pk2(bf0.w, bf0.w);
            bb[4] = pk2(bf1.x, bf1.x); bb[5] = pk2(bf1.y, bf1.y);
            bb[6] = pk2(bf1.z, bf1.z); bb[7] = pk2(bf1.w, bf1.w);
            #pragma unroll
            for (int i = 0; i < 4; i++)
                #pragma unroll
                for (int j = 0; j < 8; j++)
                    acc[i][j] = ffma2(a2[i], bb[j], acc[i][j]);
        }

        if (has_next) {
            int nb = buf ^ 1;
            As[nb][ak + 0][am] = ra0.x; As[nb][ak + 1][am] = ra0.y;
            As[nb][ak + 2][am] = ra0.z; As[nb][ak + 3][am] = ra0.w;
            As[nb][ak + 4][am] = ra1.x; As[nb][ak + 5][am] = ra1.y;
            As[nb][ak + 6][am] = ra1.z; As[nb][ak + 7][am] = ra1.w;
            if (!transB) {
                *(float4*)&Bs[nb][bk_nt][bn_nt]     = rb0;
                *(float4*)&Bs[nb][bk_nt][bn_nt + 4] = rb1;
            } else {
                Bs[nb][bk_t + 0][bn_t] = rb0.x; Bs[nb][bk_t + 1][bn_t] = rb0.y;
                Bs[nb][bk_t + 2][bn_t] = rb0.z; Bs[nb][bk_t + 3][bn_t] = rb0.w;
                Bs[nb][bk_t + 4][bn_t] = rb1.x; Bs[nb][bk_t + 5][bn_t] = rb1.y;
                Bs[nb][bk_t + 6][bn_t] = rb1.z; Bs[nb][bk_t + 7][bn_t] = rb1.w;
            }
        }
        __syncthreads();
        buf ^= 1;
    }

    // ---- epilogue ----
    #pragma unroll
    for (int i = 0; i < 4; i++) {
        #pragma unroll
        for (int j = 0; j < 8; j++) {
            float lo, hi;
            upk2(acc[i][j], lo, hi);
            int n = n0 + tx * 8 + j;
            float bv = bias ? bias[n] : 0.f;
            #pragma unroll
            for (int p = 0; p < 2; p++) {
                int lr = m0 + ty * 8 + 2 * i + p;
                if (lr >= Me) continue;
                float v = (p == 0 ? lo : hi) + bv;
                if (gelu) v = v * normcdff(v);
                long crow = (row_mode == 0) ? (long)lr : (long)list[lr];
                long ci = crow * (long)ldc + n;
                if (accum) C[ci] += v; else C[ci] = v;
            }
        }
    }
}

// ---------------------------------------------------------------------------
// Causal flash attention v2: 64 queries x 2 half-threads per block,
// batch-8 online softmax, f32x2 math.
__global__ void attn_k() {
    int h  = blockIdx.y;
    int q0 = blockIdx.x * 64;
    int t  = threadIdx.x;
    int ql = t >> 1, half = t & 1;
    int q  = q0 + ql;

    u64 qv2[16];
    {
        const float* qptr = &g_qkv[(long)q * 3072 + h * 64 + half * 32];
        #pragma unroll
        for (int i = 0; i < 8; i++) {
            ulonglong2 v = *(const ulonglong2*)&qptr[i * 4];
            qv2[2 * i] = v.x; qv2[2 * i + 1] = v.y;
        }
    }

    float m = -1e30f, l = 0.f;
    u64 acc2[16];
    #pragma unroll
    for (int i = 0; i < 16; i++) acc2[i] = 0ULL;

    __shared__ float Ks[64][64];
    __shared__ float Vs[64][64];

    for (int kt = 0; kt <= q0 + 63; kt += 64) {
        for (int i = t * 4; i < 64 * 64; i += 128 * 4) {
            int kk = i >> 6, d = i & 63;
            *(float4*)&Ks[kk][d] = *(const float4*)&g_qkv[(long)(kt + kk) * 3072 + 1024 + h * 64 + d];
            *(float4*)&Vs[kk][d] = *(const float4*)&g_qkv[(long)(kt + kk) * 3072 + 2048 + h * 64 + d];
        }
        __syncthreads();

        int kmax = q - kt + 1;
        if (kmax > 64) kmax = 64;

        for (int kb = 0; kb < 64; kb += 8) {
            // ---- 8 dot products, uniform control flow (shfl inside) ----
            float s[8];
            #pragma unroll
            for (int j = 0; j < 8; j++) {
                const u64* K2 = (const u64*)&Ks[kb + j][half * 32];
                u64 p2 = 0ULL;
                #pragma unroll
                for (int i = 0; i < 16; i++) p2 = ffma2(qv2[i], K2[i], p2);
                float lo, hi;
                upk2(p2, lo, hi);
                float p = lo + hi;
                p += __shfl_xor_sync(0xffffffffu, p, 1);
                s[j] = p * 0.125f;   // 1/sqrt(64)
            }

            int c = kmax - kb; if (c > 8) c = 8;
            if (c <= 0) continue;

            float bm = s[0];
            #pragma unroll
            for (int j = 1; j < 8; j++) if (j < c) bm = fmaxf(bm, s[j]);
            float mn = fmaxf(m, bm);
            float cor = __expf(m - mn);
            m = mn;
            l *= cor;
            u64 cor2 = pk2(cor, cor);
            #pragma unroll
            for (int i = 0; i < 16; i++) acc2[i] = fmul2(acc2[i], cor2);

            #pragma unroll
            for (int j = 0; j < 8; j++) {
                if (j >= c) break;
                float pe = __expf(s[j] - mn);
                l += pe;
                u64 pe2 = pk2(pe, pe);
                const u64* V2 = (const u64*)&Vs[kb + j][half * 32];
                #pragma unroll
                for (int i = 0; i < 16; i++) acc2[i] = ffma2(V2[i], pe2, acc2[i]);
            }
        }
        __syncthreads();
    }

    float inv = 1.f / l;
    float* optr = &g_attn[(long)q * HID + h * 64 + half * 32];
    #pragma unroll
    for (int i = 0; i < 16; i++) {
        float lo, hi;
        upk2(acc2[i], lo, hi);
        optr[2 * i]     = lo * inv;
        optr[2 * i + 1] = hi * inv;
    }
}

// ---------------------------------------------------------------------------
__global__ void zero_cnt_k() { if (threadIdx.x < NEXP) g_ecnt[threadIdx.x] = 0; }

__global__ void router_k(const float* __restrict__ rw) {
    int tok = blockIdx.x, t = threadIdx.x;   // 128 threads
    __shared__ float sm[NEXP][128];
    __shared__ float logits[NEXP];
    const float* xr = g_ln + (long)tok * HID;

    for (int e = 0; e < NEXP; e++) {
        float s = 0.f;
        for (int j = t; j < HID; j += 128) s += xr[j] * rw[e * HID + j];
        sm[e][t] = s;
    }
    __syncthreads();
    if (t < NEXP) {
        float s = 0.f;
        for (int j = 0; j < 128; j++) s += sm[t][j];
        logits[t] = s;
    }
    __syncthreads();
    if (t == 0) {
        float mx = logits[0];
        for (int e = 1; e < NEXP; e++) mx = fmaxf(mx, logits[e]);
        float p[NEXP], den = 0.f;
        for (int e = 0; e < NEXP; e++) { p[e] = expf(logits[e] - mx); den += p[e]; }
        float idn = 1.f / den;
        for (int e = 0; e < NEXP; e++) p[e] *= idn;
        int i1 = 0;
        for (int e = 1; e < NEXP; e++) if (p[e] > p[i1]) i1 = e;
        int i2 = -1;
        for (int e = 0; e < NEXP; e++) {
            if (e == i1) continue;
            if (i2 < 0 || p[e] > p[i2]) i2 = e;
        }
        g_slotw[tok * 2 + 0] = p[i1];
        g_slotw[tok * 2 + 1] = p[i2];
        int p1 = atomicAdd(&g_ecnt[i1], 1); g_elist[i1 * SQ + p1] = tok * 2 + 0;
        int p2 = atomicAdd(&g_ecnt[i2], 1); g_elist[i2 * SQ + p2] = tok * 2 + 1;
    }
}

// ---------------------------------------------------------------------------
__global__ void combine_k() {
    int tok = blockIdx.x;
    float w0 = g_slotw[tok * 2 + 0];
    float w1 = g_slotw[tok * 2 + 1];
    const float* o0 = g_out2 + (long)(tok * 2 + 0) * HID;
    const float* o1 = g_out2 + (long)(tok * 2 + 1) * HID;
    float* xr = g_x + (long)tok * HID;
    for (int h = threadIdx.x; h < HID; h += blockDim.x)
        xr[h] += w0 * o0[h] + w1 * o1[h];
}

// ---------------------------------------------------------------------------
extern "C" void kernel_launch(void* const* d_in, const int* in_sizes, int n_in,
                              void* d_out, int out_size) {
    const int*   idx  = (const int*)  d_in[0];
    const float* tok  = (const float*)d_in[1];
    const float* pos  = (const float*)d_in[2];
    const float* ln1g = (const float*)d_in[3];
    const float* ln1b = (const float*)d_in[4];
    const float* wqkv = (const float*)d_in[5];
    const float* bqkv = (const float*)d_in[6];
    const float* wo   = (const float*)d_in[7];
    const float* bo   = (const float*)d_in[8];
    const float* ln2g = (const float*)d_in[9];
    const float* ln2b = (const float*)d_in[10];
    const float* rw   = (const float*)d_in[11];
    const float* w1   = (const float*)d_in[12];
    const float* w2   = (const float*)d_in[13];
    const float* lnfg = (const float*)d_in[14];
    const float* lnfb = (const float*)d_in[15];
    float* out = (float*)d_out;

    void *px_, *pln_, *pqkv_, *pattn_, *phid_, *pout2_, *pel_, *pec_;
    cudaGetSymbolAddress(&px_,    g_x);
    cudaGetSymbolAddress(&pln_,   g_ln);
    cudaGetSymbolAddress(&pqkv_,  g_qkv);
    cudaGetSymbolAddress(&pattn_, g_attn);
    cudaGetSymbolAddress(&phid_,  g_hid);
    cudaGetSymbolAddress(&pout2_, g_out2);
    cudaGetSymbolAddress(&pel_,   g_elist);
    cudaGetSymbolAddress(&pec_,   g_ecnt);
    float* px    = (float*)px_;
    float* pln   = (float*)pln_;
    float* pqkv  = (float*)pqkv_;
    float* pattn = (float*)pattn_;
    float* phid  = (float*)phid_;
    float* pout2 = (float*)pout2_;
    const int* pel = (const int*)pel_;
    const int* pec = (const int*)pec_;

    embed_k<<<SQ, 256>>>(idx, tok, pos);

    for (int l = 0; l < NLAY; l++) {
        ln_k<<<SQ, 256>>>(px, pln, ln1g + l * HID, ln1b + l * HID);
        // qkv = x_ln @ wqkv.T + bqkv   (M=2048, N=3072, K=1024)
        sgemm_k<<<dim3(24, 16, 1), 256>>>(
            pln, HID,
            wqkv + (long)l * 3 * HID * HID, HID, 1, 0,
            bqkv + (long)l * 3 * HID,
            pqkv, 3 * HID,
            SQ, 3 * HID, HID,
            0, 0, 0, nullptr, nullptr);
        attn_k<<<dim3(SQ / 64, NHEAD), 128>>>();
        // x += attn @ wo.T + bo
        sgemm_k<<<dim3(8, 16, 1), 256>>>(
            pattn, HID,
            wo + (long)l * HID * HID, HID, 1, 0,
            bo + (long)l * HID,
            px, HID,
            SQ, HID, HID,
            1, 0, 0, nullptr, nullptr);
        ln_k<<<SQ, 256>>>(px, pln, ln2g + l * HID, ln2b + l * HID);
        zero_cnt_k<<<1, 32>>>();
        router_k<<<SQ, 128>>>(rw + (long)l * NEXP * HID);
        // hid[slot] = gelu(x_ln[token] @ w1[e])
        sgemm_k<<<dim3(FFD / 128, 16, NEXP), 256>>>(
            pln, HID,
            w1 + (long)l * NEXP * HID * FFD, FFD, 0, (long)HID * FFD,
            nullptr,
            phid, FFD,
            SQ, FFD, HID,
            0, 1, 1, pel, pec);
        // out2[slot] = hid[slot] @ w2[e]
        sgemm_k<<<dim3(HID / 128, 16, NEXP), 256>>>(
            phid, FFD,
            w2 + (long)l * NEXP * FFD * HID, HID, 0, (long)FFD * HID,
            nullptr,
            pout2, HID,
            SQ, HID, FFD,
            0, 0, 2, pel, pec);
        combine_k<<<SQ, 256>>>();
    }

    ln_k<<<SQ, 256>>>(px, pln, lnfg, lnfb);
    // logits = LN(x) @ tok_emb.T   (M=2048, N=32000, K=1024)
    sgemm_k<<<dim3(VOC / 128, 16, 1), 256>>>(
        pln, HID,
        tok, HID, 1, 0,
        nullptr,
        out, VOC,
        SQ, VOC, HID,
        0, 0, 0, nullptr, nullptr);
}

// round 7
// speedup vs baseline: 1.2743x; 1.1252x over previous
#include <cuda_runtime.h>
#include <math.h>
#include <stdint.h>

// ---- model dims ----
#define SQ   2048
#define HID  1024
#define NHEAD 16
#define HD   64
#define FFD  4096
#define NEXP 8
#define TOPK 2
#define VOC  32000
#define NLAY 2

typedef unsigned long long u64;

// ---------------- f32x2 helpers (attention) ----------------
__device__ __forceinline__ u64 pk2(float lo, float hi) {
    u64 r; asm("mov.b64 %0, {%1,%2};" : "=l"(r) : "f"(lo), "f"(hi)); return r;
}
__device__ __forceinline__ void upk2(u64 v, float& lo, float& hi) {
    asm("mov.b64 {%0,%1}, %2;" : "=f"(lo), "=f"(hi) : "l"(v));
}
__device__ __forceinline__ u64 ffma2(u64 a, u64 b, u64 c) {
    u64 d; asm("fma.rn.f32x2 %0, %1, %2, %3;" : "=l"(d) : "l"(a), "l"(b), "l"(c)); return d;
}
__device__ __forceinline__ u64 fmul2(u64 a, u64 b) {
    u64 d; asm("mul.rn.f32x2 %0, %1, %2;" : "=l"(d) : "l"(a), "l"(b)); return d;
}

// ---------------- mma helpers ----------------
__device__ __forceinline__ uint32_t tf32r(float x) {
    uint32_t r; asm("cvt.rna.tf32.f32 %0, %1;" : "=r"(r) : "f"(x)); return r;
}
// split x into hi (tf32) + lo (tf32 of residual)
__device__ __forceinline__ void tf32split(float x, uint32_t& hi, uint32_t& lo) {
    hi = tf32r(x);
    lo = tf32r(x - __uint_as_float(hi));
}
__device__ __forceinline__ void mma_tf32(float& d0, float& d1, float& d2, float& d3,
                                         uint32_t a0, uint32_t a1, uint32_t a2, uint32_t a3,
                                         uint32_t b0, uint32_t b1) {
    asm volatile(
        "mma.sync.aligned.m16n8k8.row.col.f32.tf32.tf32.f32 "
        "{%0,%1,%2,%3},{%4,%5,%6,%7},{%8,%9},{%0,%1,%2,%3};"
        : "+f"(d0), "+f"(d1), "+f"(d2), "+f"(d3)
        : "r"(a0), "r"(a1), "r"(a2), "r"(a3), "r"(b0), "r"(b1));
}

// ---- scratch (device globals) ----
__device__ float g_x   [SQ * HID];
__device__ float g_ln  [SQ * HID];
__device__ float g_qkv [SQ * 3 * HID];
__device__ float g_attn[SQ * HID];
__device__ float g_hid [SQ * TOPK * FFD];
__device__ float g_out2[SQ * TOPK * HID];
__device__ float g_slotw[SQ * TOPK];
__device__ int   g_elist[NEXP * SQ];
__device__ int   g_ecnt [NEXP];

// ---------------------------------------------------------------------------
__global__ void embed_k(const int* __restrict__ idx,
                        const float* __restrict__ tok,
                        const float* __restrict__ pos) {
    int s = blockIdx.x;
    int row = idx[s];
    for (int h = threadIdx.x; h < HID; h += blockDim.x)
        g_x[s * HID + h] = tok[(long)row * HID + h] + pos[(long)s * HID + h];
}

// ---------------------------------------------------------------------------
__global__ void ln_k(const float* __restrict__ in, float* __restrict__ out,
                     const float* __restrict__ g, const float* __restrict__ b) {
    int s = blockIdx.x, t = threadIdx.x;
    __shared__ float red[256];
    const float* row = in + (long)s * HID;

    float sum = 0.f;
    for (int h = t; h < HID; h += 256) sum += row[h];
    red[t] = sum; __syncthreads();
    for (int o = 128; o > 0; o >>= 1) { if (t < o) red[t] += red[t + o]; __syncthreads(); }
    float mu = red[0] * (1.0f / HID);
    __syncthreads();

    float vs = 0.f;
    for (int h = t; h < HID; h += 256) { float d = row[h] - mu; vs += d * d; }
    red[t] = vs; __syncthreads();
    for (int o = 128; o > 0; o >>= 1) { if (t < o) red[t] += red[t + o]; __syncthreads(); }
    float inv = rsqrtf(red[0] * (1.0f / HID) + 1e-5f);

    float* orow = out + (long)s * HID;
    for (int h = t; h < HID; h += 256)
        orow[h] = (row[h] - mu) * inv * g[h] + b[h];
}

// ---------------------------------------------------------------------------
// 3xTF32 tensor-core GEMM via mma.sync.m16n8k8 (fp32-accurate).
// 128x128x32 tile, 256 threads (8 warps, 2x4), warp tile 64x32.
// Smem: hi/lo planes for A (m-major) and B (n-major), stride 36, single-buffered;
// next chunk prefetched into registers during compute.
// row_mode: 0 direct; 1 MoE gemm1 (A row = slot/2 token, C row = slot);
//           2 MoE gemm2 (A row = slot, C row = slot).
// transB: 1 -> B[n][k]; 0 -> B[k][n] (transposed during load).
#define ABUF (128 * 36)
#define SM_TOT (4 * ABUF * 4)   // 4 planes * 128*36 u32 = 73728 B

__global__ void __launch_bounds__(256) mmagemm_k(
        const float* __restrict__ A, int lda,
        const float* __restrict__ Bmat, int ldb, int transB, long strideB,
        const float* __restrict__ bias,
        float* __restrict__ C, int ldc,
        int M, int N, int K,
        int accum, int gelu, int row_mode,
        const int* __restrict__ elist, const int* __restrict__ ecnt) {
    extern __shared__ uint32_t smem[];
    uint32_t* Ah = smem;
    uint32_t* Al = smem + ABUF;
    uint32_t* Bh = smem + 2 * ABUF;
    uint32_t* Bl = smem + 3 * ABUF;

    int e = blockIdx.z;
    const float* B = Bmat + (long)e * strideB;
    int Me = M;
    const int* list = nullptr;
    if (row_mode) { Me = ecnt[e]; list = elist + e * SQ; }
    int m0 = blockIdx.y * 128;
    if (m0 >= Me) return;
    int n0 = blockIdx.x * 128;

    int t = threadIdx.x;
    int lane = t & 31, wid = t >> 5;
    int warp_m = wid >> 2, warp_n = wid & 3;     // 2 x 4
    int g = lane >> 2, t4 = lane & 3;

    // ---- loader mappings ----
    int am = t & 127, ak = (t >> 7) * 16;        // A: row, 16 k per thread
    int lrow = m0 + am;
    const float* Aptr = nullptr;
    if (lrow < Me) {
        long gr;
        if (row_mode == 0) gr = lrow;
        else { int slot = list[lrow]; gr = (row_mode == 1) ? (slot >> 1) : slot; }
        Aptr = A + gr * (long)lda;
    }
    int bn = t & 127, bk = (t >> 7) * 16;

    float4 ra[4], rb[4];
    float  rbs[16];
    const float4 z4 = make_float4(0.f, 0.f, 0.f, 0.f);

    float acc[4][4][4];
    #pragma unroll
    for (int i = 0; i < 4; i++)
        #pragma unroll
        for (int j = 0; j < 4; j++)
            #pragma unroll
            for (int c = 0; c < 4; c++) acc[i][j][c] = 0.f;

    int nch = K / 32;

    auto load_chunk = [&](int k0) {
        #pragma unroll
        for (int q = 0; q < 4; q++)
            ra[q] = Aptr ? *(const float4*)&Aptr[k0 + ak + 4 * q] : z4;
        if (transB) {
            #pragma unroll
            for (int q = 0; q < 4; q++)
                rb[q] = *(const float4*)&B[(long)(n0 + bn) * ldb + k0 + bk + 4 * q];
        } else {
            #pragma unroll
            for (int j = 0; j < 16; j++)
                rbs[j] = B[(long)(k0 + bk + j) * ldb + n0 + bn];
        }
    };
    auto store_chunk = [&]() {
        uint32_t* dah = Ah + am * 36 + ak;
        uint32_t* dal = Al + am * 36 + ak;
        #pragma unroll
        for (int q = 0; q < 4; q++) {
            const float* f = (const float*)&ra[q];
            uint4 wh, wl;
            tf32split(f[0], wh.x, wl.x); tf32split(f[1], wh.y, wl.y);
            tf32split(f[2], wh.z, wl.z); tf32split(f[3], wh.w, wl.w);
            *(uint4*)(dah + 4 * q) = wh;
            *(uint4*)(dal + 4 * q) = wl;
        }
        uint32_t* dbh = Bh + bn * 36 + bk;
        uint32_t* dbl = Bl + bn * 36 + bk;
        if (transB) {
            #pragma unroll
            for (int q = 0; q < 4; q++) {
                const float* f = (const float*)&rb[q];
                uint4 wh, wl;
                tf32split(f[0], wh.x, wl.x); tf32split(f[1], wh.y, wl.y);
                tf32split(f[2], wh.z, wl.z); tf32split(f[3], wh.w, wl.w);
                *(uint4*)(dbh + 4 * q) = wh;
                *(uint4*)(dbl + 4 * q) = wl;
            }
        } else {
            #pragma unroll
            for (int q = 0; q < 4; q++) {
                uint4 wh, wl;
                tf32split(rbs[4 * q + 0], wh.x, wl.x); tf32split(rbs[4 * q + 1], wh.y, wl.y);
                tf32split(rbs[4 * q + 2], wh.z, wl.z); tf32split(rbs[4 * q + 3], wh.w, wl.w);
                *(uint4*)(dbh + 4 * q) = wh;
                *(uint4*)(dbl + 4 * q) = wl;
            }
        }
    };

    load_chunk(0);
    store_chunk();
    __syncthreads();

    for (int c = 0; c < nch; c++) {
        int has_next = (c + 1 < nch);
        if (has_next) load_chunk((c + 1) * 32);

        const uint32_t* pah = Ah + (warp_m * 64) * 36;
        const uint32_t* pal = Al + (warp_m * 64) * 36;
        const uint32_t* pbh = Bh + (warp_n * 32) * 36;
        const uint32_t* pbl = Bl + (warp_n * 32) * 36;
        #pragma unroll
        for (int ks = 0; ks < 4; ks++) {
            int k = ks * 8;
            uint32_t afh[4][4], afl[4][4], bfh[4][2], bfl[4][2];
            #pragma unroll
            for (int mt = 0; mt < 4; mt++) {
                int r0 = (mt * 16 + g) * 36 + k + t4;
                int r1 = (mt * 16 + g + 8) * 36 + k + t4;
                afh[mt][0] = pah[r0]; afh[mt][1] = pah[r1];
                afh[mt][2] = pah[r0 + 4]; afh[mt][3] = pah[r1 + 4];
                afl[mt][0] = pal[r0]; afl[mt][1] = pal[r1];
                afl[mt][2] = pal[r0 + 4]; afl[mt][3] = pal[r1 + 4];
            }
            #pragma unroll
            for (int nt = 0; nt < 4; nt++) {
                int r = (nt * 8 + g) * 36 + k + t4;
                bfh[nt][0] = pbh[r]; bfh[nt][1] = pbh[r + 4];
                bfl[nt][0] = pbl[r]; bfl[nt][1] = pbl[r + 4];
            }
            #pragma unroll
            for (int mt = 0; mt < 4; mt++)
                #pragma unroll
                for (int nt = 0; nt < 4; nt++) {
                    float* a = acc[mt][nt];
                    mma_tf32(a[0], a[1], a[2], a[3],
                             afh[mt][0], afh[mt][1], afh[mt][2], afh[mt][3],
                             bfh[nt][0], bfh[nt][1]);
                    mma_tf32(a[0], a[1], a[2], a[3],
                             afh[mt][0], afh[mt][1], afh[mt][2], afh[mt][3],
                             bfl[nt][0], bfl[nt][1]);
                    mma_tf32(a[0], a[1], a[2], a[3],
                             afl[mt][0], afl[mt][1], afl[mt][2], afl[mt][3],
                             bfh[nt][0], bfh[nt][1]);
                }
        }
        __syncthreads();
        if (has_next) {
            store_chunk();
            __syncthreads();
        }
    }

    // ---- epilogue ----
    #pragma unroll
    for (int mt = 0; mt < 4; mt++) {
        int rbase = warp_m * 64 + mt * 16 + g;
        #pragma unroll
        for (int p = 0; p < 2; p++) {
            int lr = m0 + rbase + 8 * p;
            if (lr >= Me) continue;
            long crow = row_mode ? (long)list[lr] : (long)lr;
            float* cp = C + crow * (long)ldc + n0 + warp_n * 32;
            const float* bp = bias ? bias + n0 + warp_n * 32 : nullptr;
            #pragma unroll
            for (int nt = 0; nt < 4; nt++) {
                int col = nt * 8 + 2 * t4;
                float v0 = acc[mt][nt][2 * p];
                float v1 = acc[mt][nt][2 * p + 1];
                if (bp) { v0 += bp[col]; v1 += bp[col + 1]; }
                if (gelu) { v0 = v0 * normcdff(v0); v1 = v1 * normcdff(v1); }
                if (accum) { v0 += cp[col]; v1 += cp[col + 1]; }
                float2 v = make_float2(v0, v1);
                *(float2*)&cp[col] = v;
            }
        }
    }
}

// ---------------------------------------------------------------------------
// Causal flash attention: 64 q x 2 half-threads, batch-8 online softmax, f32x2.
__global__ void attn_k() {
    int h  = blockIdx.y;
    int q0 = blockIdx.x * 64;
    int t  = threadIdx.x;
    int ql = t >> 1, half = t & 1;
    int q  = q0 + ql;

    u64 qv2[16];
    {
        const float* qptr = &g_qkv[(long)q * 3072 + h * 64 + half * 32];
        #pragma unroll
        for (int i = 0; i < 8; i++) {
            ulonglong2 v = *(const ulonglong2*)&qptr[i * 4];
            qv2[2 * i] = v.x; qv2[2 * i + 1] = v.y;
        }
    }

    float m = -1e30f, l = 0.f;
    u64 acc2[16];
    #pragma unroll
    for (int i = 0; i < 16; i++) acc2[i] = 0ULL;

    __shared__ float Ks[64][64];
    __shared__ float Vs[64][64];

    for (int kt = 0; kt <= q0 + 63; kt += 64) {
        for (int i = t * 4; i < 64 * 64; i += 128 * 4) {
            int kk = i >> 6, d = i & 63;
            *(float4*)&Ks[kk][d] = *(const float4*)&g_qkv[(long)(kt + kk) * 3072 + 1024 + h * 64 + d];
            *(float4*)&Vs[kk][d] = *(const float4*)&g_qkv[(long)(kt + kk) * 3072 + 2048 + h * 64 + d];
        }
        __syncthreads();

        int kmax = q - kt + 1;
        if (kmax > 64) kmax = 64;

        for (int kb = 0; kb < 64; kb += 8) {
            float s[8];
            #pragma unroll
            for (int j = 0; j < 8; j++) {
                const u64* K2 = (const u64*)&Ks[kb + j][half * 32];
                u64 p2 = 0ULL;
                #pragma unroll
                for (int i = 0; i < 16; i++) p2 = ffma2(qv2[i], K2[i], p2);
                float lo, hi;
                upk2(p2, lo, hi);
                float p = lo + hi;
                p += __shfl_xor_sync(0xffffffffu, p, 1);
                s[j] = p * 0.125f;
            }

            int c = kmax - kb; if (c > 8) c = 8;
            if (c <= 0) continue;

            float bm = s[0];
            #pragma unroll
            for (int j = 1; j < 8; j++) if (j < c) bm = fmaxf(bm, s[j]);
            float mn = fmaxf(m, bm);
            float cor = __expf(m - mn);
            m = mn;
            l *= cor;
            u64 cor2 = pk2(cor, cor);
            #pragma unroll
            for (int i = 0; i < 16; i++) acc2[i] = fmul2(acc2[i], cor2);

            #pragma unroll
            for (int j = 0; j < 8; j++) {
                if (j >= c) break;
                float pe = __expf(s[j] - mn);
                l += pe;
                u64 pe2 = pk2(pe, pe);
                const u64* V2 = (const u64*)&Vs[kb + j][half * 32];
                #pragma unroll
                for (int i = 0; i < 16; i++) acc2[i] = ffma2(V2[i], pe2, acc2[i]);
            }
        }
        __syncthreads();
    }

    float inv = 1.f / l;
    float* optr = &g_attn[(long)q * HID + h * 64 + half * 32];
    #pragma unroll
    for (int i = 0; i < 16; i++) {
        float lo, hi;
        upk2(acc2[i], lo, hi);
        optr[2 * i]     = lo * inv;
        optr[2 * i + 1] = hi * inv;
    }
}

// ---------------------------------------------------------------------------
__global__ void zero_cnt_k() { if (threadIdx.x < NEXP) g_ecnt[threadIdx.x] = 0; }

__global__ void router_k(const float* __restrict__ rw) {
    int tok = blockIdx.x, t = threadIdx.x;   // 128 threads
    __shared__ float sm[NEXP][128];
    __shared__ float logits[NEXP];
    const float* xr = g_ln + (long)tok * HID;

    for (int e = 0; e < NEXP; e++) {
        float s = 0.f;
        for (int j = t; j < HID; j += 128) s += xr[j] * rw[e * HID + j];
        sm[e][t] = s;
    }
    __syncthreads();
    if (t < NEXP) {
        float s = 0.f;
        for (int j = 0; j < 128; j++) s += sm[t][j];
        logits[t] = s;
    }
    __syncthreads();
    if (t == 0) {
        float mx = logits[0];
        for (int e = 1; e < NEXP; e++) mx = fmaxf(mx, logits[e]);
        float p[NEXP], den = 0.f;
        for (int e = 0; e < NEXP; e++) { p[e] = expf(logits[e] - mx); den += p[e]; }
        float idn = 1.f / den;
        for (int e = 0; e < NEXP; e++) p[e] *= idn;
        int i1 = 0;
        for (int e = 1; e < NEXP; e++) if (p[e] > p[i1]) i1 = e;
        int i2 = -1;
        for (int e = 0; e < NEXP; e++) {
            if (e == i1) continue;
            if (i2 < 0 || p[e] > p[i2]) i2 = e;
        }
        g_slotw[tok * 2 + 0] = p[i1];
        g_slotw[tok * 2 + 1] = p[i2];
        int p1 = atomicAdd(&g_ecnt[i1], 1); g_elist[i1 * SQ + p1] = tok * 2 + 0;
        int p2 = atomicAdd(&g_ecnt[i2], 1); g_elist[i2 * SQ + p2] = tok * 2 + 1;
    }
}

// ---------------------------------------------------------------------------
__global__ void combine_k() {
    int tok = blockIdx.x;
    float w0 = g_slotw[tok * 2 + 0];
    float w1 = g_slotw[tok * 2 + 1];
    const float* o0 = g_out2 + (long)(tok * 2 + 0) * HID;
    const float* o1 = g_out2 + (long)(tok * 2 + 1) * HID;
    float* xr = g_x + (long)tok * HID;
    for (int h = threadIdx.x; h < HID; h += blockDim.x)
        xr[h] += w0 * o0[h] + w1 * o1[h];
}

// ---------------------------------------------------------------------------
extern "C" void kernel_launch(void* const* d_in, const int* in_sizes, int n_in,
                              void* d_out, int out_size) {
    const int*   idx  = (const int*)  d_in[0];
    const float* tok  = (const float*)d_in[1];
    const float* pos  = (const float*)d_in[2];
    const float* ln1g = (const float*)d_in[3];
    const float* ln1b = (const float*)d_in[4];
    const float* wqkv = (const float*)d_in[5];
    const float* bqkv = (const float*)d_in[6];
    const float* wo   = (const float*)d_in[7];
    const float* bo   = (const float*)d_in[8];
    const float* ln2g = (const float*)d_in[9];
    const float* ln2b = (const float*)d_in[10];
    const float* rw   = (const float*)d_in[11];
    const float* w1   = (const float*)d_in[12];
    const float* w2   = (const float*)d_in[13];
    const float* lnfg = (const float*)d_in[14];
    const float* lnfb = (const float*)d_in[15];
    float* out = (float*)d_out;

    cudaFuncSetAttribute(mmagemm_k, cudaFuncAttributeMaxDynamicSharedMemorySize, SM_TOT);

    void *px_, *pln_, *pqkv_, *pattn_, *phid_, *pout2_, *pel_, *pec_;
    cudaGetSymbolAddress(&px_,    g_x);
    cudaGetSymbolAddress(&pln_,   g_ln);
    cudaGetSymbolAddress(&pqkv_,  g_qkv);
    cudaGetSymbolAddress(&pattn_, g_attn);
    cudaGetSymbolAddress(&phid_,  g_hid);
    cudaGetSymbolAddress(&pout2_, g_out2);
    cudaGetSymbolAddress(&pel_,   g_elist);
    cudaGetSymbolAddress(&pec_,   g_ecnt);
    float* px    = (float*)px_;
    float* pln   = (float*)pln_;
    float* pqkv  = (float*)pqkv_;
    float* pattn = (float*)pattn_;
    float* phid  = (float*)phid_;
    float* pout2 = (float*)pout2_;
    const int* pel = (const int*)pel_;
    const int* pec = (const int*)pec_;

    embed_k<<<SQ, 256>>>(idx, tok, pos);

    for (int l = 0; l < NLAY; l++) {
        ln_k<<<SQ, 256>>>(px, pln, ln1g + l * HID, ln1b + l * HID);
        // qkv = x_ln @ wqkv.T + bqkv  (M=2048, N=3072, K=1024; wqkv [N,K] -> transB=1)
        mmagemm_k<<<dim3(24, 16, 1), 256, SM_TOT>>>(
            pln, HID,
            wqkv + (long)l * 3 * HID * HID, HID, 1, 0,
            bqkv + (long)l * 3 * HID,
            pqkv, 3 * HID,
            SQ, 3 * HID, HID,
            0, 0, 0, nullptr, nullptr);
        attn_k<<<dim3(SQ / 64, NHEAD), 128>>>();
        // x += attn @ wo.T + bo  (M=2048, N=1024, K=1024)
        mmagemm_k<<<dim3(8, 16, 1), 256, SM_TOT>>>(
            pattn, HID,
            wo + (long)l * HID * HID, HID, 1, 0,
            bo + (long)l * HID,
            px, HID,
            SQ, HID, HID,
            1, 0, 0, nullptr, nullptr);
        ln_k<<<SQ, 256>>>(px, pln, ln2g + l * HID, ln2b + l * HID);
        zero_cnt_k<<<1, 32>>>();
        router_k<<<SQ, 128>>>(rw + (long)l * NEXP * HID);
        // hid[slot] = gelu(x_ln[token] @ w1[e])  (w1 [K,N] -> transB=0)
        mmagemm_k<<<dim3(FFD / 128, 16, NEXP), 256, SM_TOT>>>(
            pln, HID,
            w1 + (long)l * NEXP * HID * FFD, FFD, 0, (long)HID * FFD,
            nullptr,
            phid, FFD,
            SQ, FFD, HID,
            0, 1, 1, pel, pec);
        // out2[slot] = hid[slot] @ w2[e]  (w2 [K,N] -> transB=0)
        mmagemm_k<<<dim3(HID / 128, 16, NEXP), 256, SM_TOT>>>(
            phid, FFD,
            w2 + (long)l * NEXP * FFD * HID, HID, 0, (long)FFD * HID,
            nullptr,
            pout2, HID,
            SQ, HID, FFD,
            0, 0, 2, pel, pec);
        combine_k<<<SQ, 256>>>();
    }

    ln_k<<<SQ, 256>>>(px, pln, lnfg, lnfb);
    // logits = LN(x) @ tok_emb.T  (M=2048, N=32000, K=1024; tok [N,K] -> transB=1)
    mmagemm_k<<<dim3(VOC / 128, 16, 1), 256, SM_TOT>>>(
        pln, HID,
        tok, HID, 1, 0,
        nullptr,
        out, VOC,
        SQ, VOC, HID,
        0, 0, 0, nullptr, nullptr);
}

// round 9
// speedup vs baseline: 1.4806x; 1.1618x over previous
#include <cuda_runtime.h>
#include <cuda_bf16.h>
#include <math.h>
#include <stdint.h>

// ---- model dims ----
#define SQ   2048
#define HID  1024
#define NHEAD 16
#define HD   64
#define FFD  4096
#define NEXP 8
#define TOPK 2
#define VOC  32000
#define NLAY 2

typedef unsigned long long u64;

// ---------------- f32x2 helpers (attention) ----------------
__device__ __forceinline__ u64 pk2(float lo, float hi) {
    u64 r; asm("mov.b64 %0, {%1,%2};" : "=l"(r) : "f"(lo), "f"(hi)); return r;
}
__device__ __forceinline__ void upk2(u64 v, float& lo, float& hi) {
    asm("mov.b64 {%0,%1}, %2;" : "=f"(lo), "=f"(hi) : "l"(v));
}
__device__ __forceinline__ u64 ffma2(u64 a, u64 b, u64 c) {
    u64 d; asm("fma.rn.f32x2 %0, %1, %2, %3;" : "=l"(d) : "l"(a), "l"(b), "l"(c)); return d;
}
__device__ __forceinline__ u64 fmul2(u64 a, u64 b) {
    u64 d; asm("mul.rn.f32x2 %0, %1, %2;" : "=l"(d) : "l"(a), "l"(b)); return d;
}

// ---------------- bf16 mma helpers ----------------
// Split (x0,x1) into packed bf16x2 hi and lo planes: x ~= hi + lo.
__device__ __forceinline__ void bfsplit2(float x0, float x1, uint32_t& h, uint32_t& l) {
    __nv_bfloat16 h0 = __float2bfloat16(x0);
    __nv_bfloat16 h1 = __float2bfloat16(x1);
    float r0 = x0 - __bfloat162float(h0);
    float r1 = x1 - __bfloat162float(h1);
    __nv_bfloat16 l0 = __float2bfloat16(r0);
    __nv_bfloat16 l1 = __float2bfloat16(r1);
    h = ((uint32_t)__bfloat16_as_ushort(h1) << 16) | (uint32_t)__bfloat16_as_ushort(h0);
    l = ((uint32_t)__bfloat16_as_ushort(l1) << 16) | (uint32_t)__bfloat16_as_ushort(l0);
}
__device__ __forceinline__ void mma_bf16(float& d0, float& d1, float& d2, float& d3,
                                         uint32_t a0, uint32_t a1, uint32_t a2, uint32_t a3,
                                         uint32_t b0, uint32_t b1) {
    asm volatile(
        "mma.sync.aligned.m16n8k16.row.col.f32.bf16.bf16.f32 "
        "{%0,%1,%2,%3},{%4,%5,%6,%7},{%8,%9},{%0,%1,%2,%3};"
        : "+f"(d0), "+f"(d1), "+f"(d2), "+f"(d3)
        : "r"(a0), "r"(a1), "r"(a2), "r"(a3), "r"(b0), "r"(b1));
}

// ---- scratch (device globals) ----
__device__ float g_x   [SQ * HID];
__device__ float g_ln  [SQ * HID];
__device__ float g_qkv [SQ * 3 * HID];
__device__ float g_attn[SQ * HID];
__device__ float g_hid [SQ * TOPK * FFD];
__device__ float g_out2[SQ * TOPK * HID];
__device__ float g_slotw[SQ * TOPK];
__device__ int   g_elist[NEXP * SQ];
__device__ int   g_ecnt [NEXP];

// ---------------------------------------------------------------------------
__global__ void embed_k(const int* __restrict__ idx,
                        const float* __restrict__ tok,
                        const float* __restrict__ pos) {
    int s = blockIdx.x;
    int row = idx[s];
    for (int h = threadIdx.x; h < HID; h += blockDim.x)
        g_x[s * HID + h] = tok[(long)row * HID + h] + pos[(long)s * HID + h];
}

// ---------------------------------------------------------------------------
__global__ void ln_k(const float* __restrict__ in, float* __restrict__ out,
                     const float* __restrict__ g, const float* __restrict__ b) {
    int s = blockIdx.x, t = threadIdx.x;
    __shared__ float red[256];
    const float* row = in + (long)s * HID;

    float sum = 0.f;
    for (int h = t; h < HID; h += 256) sum += row[h];
    red[t] = sum; __syncthreads();
    for (int o = 128; o > 0; o >>= 1) { if (t < o) red[t] += red[t + o]; __syncthreads(); }
    float mu = red[0] * (1.0f / HID);
    __syncthreads();

    float vs = 0.f;
    for (int h = t; h < HID; h += 256) { float d = row[h] - mu; vs += d * d; }
    red[t] = vs; __syncthreads();
    for (int o = 128; o > 0; o >>= 1) { if (t < o) red[t] += red[t + o]; __syncthreads(); }
    float inv = rsqrtf(red[0] * (1.0f / HID) + 1e-5f);

    float* orow = out + (long)s * HID;
    for (int h = t; h < HID; h += 256)
        orow[h] = (row[h] - mu) * inv * g[h] + b[h];
}

// ---------------------------------------------------------------------------
// 4-term bf16 tensor-core GEMM via mma.sync.m16n8k16 (fp32-accurate to ~2^-18).
// 128x128x32 tile, 256 threads (8 warps, 2x4), warp tile 64x32, double-buffered.
// Smem u32 planes: values packed as bf16x2 along k; row stride 20 u32
// (fragment loads bank-conflict-free: {20g mod 32} all-distinct).
// row_mode: 0 direct; 1 MoE gemm1 (A row = slot/2 token, C row = slot);
//           2 MoE gemm2 (A row = slot, C row = slot).
// transB: 1 -> B[n][k]; 0 -> B[k][n] (transposed during load).
#define ASTRIDE 20
#define PLANE   (128 * ASTRIDE)      // u32 per plane
#define BUFU32  (4 * PLANE)          // Ah, Al, Bh, Bl
#define SM_TOT  (2 * BUFU32 * 4)     // bytes = 81920

__global__ void __launch_bounds__(256) bfgemm_k(
        const float* __restrict__ A, int lda,
        const float* __restrict__ Bmat, int ldb, int transB, long strideB,
        const float* __restrict__ bias,
        float* __restrict__ C, int ldc,
        int M, int N, int K,
        int accum, int gelu, int row_mode,
        const int* __restrict__ elist, const int* __restrict__ ecnt) {
    extern __shared__ uint32_t smem[];

    int e = blockIdx.z;
    const float* B = Bmat + (long)e * strideB;
    int Me = M;
    const int* list = nullptr;
    if (row_mode) { Me = ecnt[e]; list = elist + e * SQ; }
    int m0 = blockIdx.y * 128;
    if (m0 >= Me) return;
    int n0 = blockIdx.x * 128;

    int t = threadIdx.x;
    int lane = t & 31, wid = t >> 5;
    int warp_m = wid >> 2, warp_n = wid & 3;     // 2 x 4
    int g = lane >> 2, t4 = lane & 3;

    // ---- loader mappings: each thread loads 16 consecutive k for one row ----
    int am = t & 127, ak = (t >> 7) * 16;
    int lrow = m0 + am;
    const float* Aptr = nullptr;
    if (lrow < Me) {
        long gr;
        if (row_mode == 0) gr = lrow;
        else { int slot = list[lrow]; gr = (row_mode == 1) ? (slot >> 1) : slot; }
        Aptr = A + gr * (long)lda;
    }
    int bn = t & 127, bk = (t >> 7) * 16;

    float ra[16], rbv[16];
    float acc[4][4][4];
    #pragma unroll
    for (int i = 0; i < 4; i++)
        #pragma unroll
        for (int j = 0; j < 4; j++)
            #pragma unroll
            for (int c = 0; c < 4; c++) acc[i][j][c] = 0.f;

    int nch = K / 32;

    auto load_chunk = [&](int k0) {
        if (Aptr) {
            #pragma unroll
            for (int q = 0; q < 4; q++) {
                float4 v = *(const float4*)&Aptr[k0 + ak + 4 * q];
                ra[4 * q] = v.x; ra[4 * q + 1] = v.y; ra[4 * q + 2] = v.z; ra[4 * q + 3] = v.w;
            }
        } else {
            #pragma unroll
            for (int j = 0; j < 16; j++) ra[j] = 0.f;
        }
        if (transB) {
            #pragma unroll
            for (int q = 0; q < 4; q++) {
                float4 v = *(const float4*)&B[(long)(n0 + bn) * ldb + k0 + bk + 4 * q];
                rbv[4 * q] = v.x; rbv[4 * q + 1] = v.y; rbv[4 * q + 2] = v.z; rbv[4 * q + 3] = v.w;
            }
        } else {
            #pragma unroll
            for (int j = 0; j < 16; j++)
                rbv[j] = B[(long)(k0 + bk + j) * ldb + n0 + bn];
        }
    };

    auto store_chunk = [&](int b) {
        uint32_t* Ah = smem + b * BUFU32;
        uint32_t* Al = Ah + PLANE;
        uint32_t* Bh = Al + PLANE;
        uint32_t* Bl = Bh + PLANE;
        uint32_t hbuf[8], lbuf[8];
        #pragma unroll
        for (int q = 0; q < 8; q++)
            bfsplit2(ra[2 * q], ra[2 * q + 1], hbuf[q], lbuf[q]);
        uint32_t* da = Ah + am * ASTRIDE + (ak >> 1);
        uint32_t* dal = Al + am * ASTRIDE + (ak >> 1);
        *(uint4*)da        = *(uint4*)&hbuf[0];
        *(uint4*)(da + 4)  = *(uint4*)&hbuf[4];
        *(uint4*)dal       = *(uint4*)&lbuf[0];
        *(uint4*)(dal + 4) = *(uint4*)&lbuf[4];
        #pragma unroll
        for (int q = 0; q < 8; q++)
            bfsplit2(rbv[2 * q], rbv[2 * q + 1], hbuf[q], lbuf[q]);
        uint32_t* db  = Bh + bn * ASTRIDE + (bk >> 1);
        uint32_t* dbl = Bl + bn * ASTRIDE + (bk >> 1);
        *(uint4*)db        = *(uint4*)&hbuf[0];
        *(uint4*)(db + 4)  = *(uint4*)&hbuf[4];
        *(uint4*)dbl       = *(uint4*)&lbuf[0];
        *(uint4*)(dbl + 4) = *(uint4*)&lbuf[4];
    };

    load_chunk(0);
    store_chunk(0);
    __syncthreads();

    for (int c = 0; c < nch; c++) {
        int b = c & 1;
        int has_next = (c + 1 < nch);
        if (has_next) load_chunk((c + 1) * 32);

        const uint32_t* Ah = smem + b * BUFU32;
        const uint32_t* Al = Ah + PLANE;
        const uint32_t* Bh = Al + PLANE;
        const uint32_t* Bl = Bh + PLANE;
        const uint32_t* pah = Ah + (warp_m * 64) * ASTRIDE;
        const uint32_t* pal = Al + (warp_m * 64) * ASTRIDE;
        const uint32_t* pbh = Bh + (warp_n * 32) * ASTRIDE;
        const uint32_t* pbl = Bl + (warp_n * 32) * ASTRIDE;

        #pragma unroll
        for (int ks = 0; ks < 2; ks++) {
            int kc = ks * 8;
            uint32_t afh[4][4], afl[4][4], bfh[4][2], bfl[4][2];
            #pragma unroll
            for (int mt = 0; mt < 4; mt++) {
                int r0 = (mt * 16 + g) * ASTRIDE + kc + t4;
                int r1 = (mt * 16 + g + 8) * ASTRIDE + kc + t4;
                afh[mt][0] = pah[r0]; afh[mt][1] = pah[r1];
                afh[mt][2] = pah[r0 + 4]; afh[mt][3] = pah[r1 + 4];
                afl[mt][0] = pal[r0]; afl[mt][1] = pal[r1];
                afl[mt][2] = pal[r0 + 4]; afl[mt][3] = pal[r1 + 4];
            }
            #pragma unroll
            for (int nt = 0; nt < 4; nt++) {
                int r = (nt * 8 + g) * ASTRIDE + kc + t4;
                bfh[nt][0] = pbh[r]; bfh[nt][1] = pbh[r + 4];
                bfl[nt][0] = pbl[r]; bfl[nt][1] = pbl[r + 4];
            }
            #pragma unroll
            for (int mt = 0; mt < 4; mt++)
                #pragma unroll
                for (int nt = 0; nt < 4; nt++) {
                    float* a = acc[mt][nt];
                    mma_bf16(a[0], a[1], a[2], a[3],
                             afh[mt][0], afh[mt][1], afh[mt][2], afh[mt][3],
                             bfh[nt][0], bfh[nt][1]);
                    mma_bf16(a[0], a[1], a[2], a[3],
                             afh[mt][0], afh[mt][1], afh[mt][2], afh[mt][3],
                             bfl[nt][0], bfl[nt][1]);
                    mma_bf16(a[0], a[1], a[2], a[3],
                             afl[mt][0], afl[mt][1], afl[mt][2], afl[mt][3],
                             bfh[nt][0], bfh[nt][1]);
                    mma_bf16(a[0], a[1], a[2], a[3],
                             afl[mt][0], afl[mt][1], afl[mt][2], afl[mt][3],
                             bfl[nt][0], bfl[nt][1]);
                }
        }

        if (has_next) store_chunk(b ^ 1);
        __syncthreads();
    }

    // ---- epilogue ----
    #pragma unroll
    for (int mt = 0; mt < 4; mt++) {
        int rbase = warp_m * 64 + mt * 16 + g;
        #pragma unroll
        for (int p = 0; p < 2; p++) {
            int lr = m0 + rbase + 8 * p;
            if (lr >= Me) continue;
            long crow = row_mode ? (long)list[lr] : (long)lr;
            float* cp = C + crow * (long)ldc + n0 + warp_n * 32;
            const float* bp = bias ? bias + n0 + warp_n * 32 : nullptr;
            #pragma unroll
            for (int nt = 0; nt < 4; nt++) {
                int col = nt * 8 + 2 * t4;
                float v0 = acc[mt][nt][2 * p];
                float v1 = acc[mt][nt][2 * p + 1];
                if (bp) { v0 += bp[col]; v1 += bp[col + 1]; }
                if (gelu) { v0 = v0 * normcdff(v0); v1 = v1 * normcdff(v1); }
                if (accum) { v0 += cp[col]; v1 += cp[col + 1]; }
                float2 v = make_float2(v0, v1);
                *(float2*)&cp[col] = v;
            }
        }
    }
}

// ---------------------------------------------------------------------------
// Causal flash attention: 64 q x 2 half-threads, batch-8 online softmax, f32x2.
__global__ void attn_k() {
    int h  = blockIdx.y;
    int q0 = blockIdx.x * 64;
    int t  = threadIdx.x;
    int ql = t >> 1, half = t & 1;
    int q  = q0 + ql;

    u64 qv2[16];
    {
        const float* qptr = &g_qkv[(long)q * 3072 + h * 64 + half * 32];
        #pragma unroll
        for (int i = 0; i < 8; i++) {
            ulonglong2 v = *(const ulonglong2*)&qptr[i * 4];
            qv2[2 * i] = v.x; qv2[2 * i + 1] = v.y;
        }
    }

    float m = -1e30f, l = 0.f;
    u64 acc2[16];
    #pragma unroll
    for (int i = 0; i < 16; i++) acc2[i] = 0ULL;

    __shared__ float Ks[64][64];
    __shared__ float Vs[64][64];

    for (int kt = 0; kt <= q0 + 63; kt += 64) {
        for (int i = t * 4; i < 64 * 64; i += 128 * 4) {
            int kk = i >> 6, d = i & 63;
            *(float4*)&Ks[kk][d] = *(const float4*)&g_qkv[(long)(kt + kk) * 3072 + 1024 + h * 64 + d];
            *(float4*)&Vs[kk][d] = *(const float4*)&g_qkv[(long)(kt + kk) * 3072 + 2048 + h * 64 + d];
        }
        __syncthreads();

        int kmax = q - kt + 1;
        if (kmax > 64) kmax = 64;

        for (int kb = 0; kb < 64; kb += 8) {
            float s[8];
            #pragma unroll
            for (int j = 0; j < 8; j++) {
                const u64* K2 = (const u64*)&Ks[kb + j][half * 32];
                u64 p2 = 0ULL;
                #pragma unroll
                for (int i = 0; i < 16; i++) p2 = ffma2(qv2[i], K2[i], p2);
                float lo, hi;
                upk2(p2, lo, hi);
                float p = lo + hi;
                p += __shfl_xor_sync(0xffffffffu, p, 1);
                s[j] = p * 0.125f;
            }

            int c = kmax - kb; if (c > 8) c = 8;
            if (c <= 0) continue;

            float bm = s[0];
            #pragma unroll
            for (int j = 1; j < 8; j++) if (j < c) bm = fmaxf(bm, s[j]);
            float mn = fmaxf(m, bm);
            float cor = __expf(m - mn);
            m = mn;
            l *= cor;
            u64 cor2 = pk2(cor, cor);
            #pragma unroll
            for (int i = 0; i < 16; i++) acc2[i] = fmul2(acc2[i], cor2);

            #pragma unroll
            for (int j = 0; j < 8; j++) {
                if (j >= c) break;
                float pe = __expf(s[j] - mn);
                l += pe;
                u64 pe2 = pk2(pe, pe);
                const u64* V2 = (const u64*)&Vs[kb + j][half * 32];
                #pragma unroll
                for (int i = 0; i < 16; i++) acc2[i] = ffma2(V2[i], pe2, acc2[i]);
            }
        }
        __syncthreads();
    }

    float inv = 1.f / l;
    float* optr = &g_attn[(long)q * HID + h * 64 + half * 32];
    #pragma unroll
    for (int i = 0; i < 16; i++) {
        float lo, hi;
        upk2(acc2[i], lo, hi);
        optr[2 * i]     = lo * inv;
        optr[2 * i + 1] = hi * inv;
    }
}

// ---------------------------------------------------------------------------
__global__ void zero_cnt_k() { if (threadIdx.x < NEXP) g_ecnt[threadIdx.x] = 0; }

__global__ void router_k(const float* __restrict__ rw) {
    int tok = blockIdx.x, t = threadIdx.x;   // 128 threads
    __shared__ float sm[NEXP][128];
    __shared__ float logits[NEXP];
    const float* xr = g_ln + (long)tok * HID;

    for (int e = 0; e < NEXP; e++) {
        float s = 0.f;
        for (int j = t; j < HID; j += 128) s += xr[j] * rw[e * HID + j];
        sm[e][t] = s;
    }
    __syncthreads();
    if (t < NEXP) {
        float s = 0.f;
        for (int j = 0; j < 128; j++) s += sm[t][j];
        logits[t] = s;
    }
    __syncthreads();
    if (t == 0) {
        float mx = logits[0];
        for (int e = 1; e < NEXP; e++) mx = fmaxf(mx, logits[e]);
        float p[NEXP], den = 0.f;
        for (int e = 0; e < NEXP; e++) { p[e] = expf(logits[e] - mx); den += p[e]; }
        float idn = 1.f / den;
        for (int e = 0; e < NEXP; e++) p[e] *= idn;
        int i1 = 0;
        for (int e = 1; e < NEXP; e++) if (p[e] > p[i1]) i1 = e;
        int i2 = -1;
        for (int e = 0; e < NEXP; e++) {
            if (e == i1) continue;
            if (i2 < 0 || p[e] > p[i2]) i2 = e;
        }
        g_slotw[tok * 2 + 0] = p[i1];
        g_slotw[tok * 2 + 1] = p[i2];
        int p1 = atomicAdd(&g_ecnt[i1], 1); g_elist[i1 * SQ + p1] = tok * 2 + 0;
        int p2 = atomicAdd(&g_ecnt[i2], 1); g_elist[i2 * SQ + p2] = tok * 2 + 1;
    }
}

// ---------------------------------------------------------------------------
__global__ void combine_k() {
    int tok = blockIdx.x;
    float w0 = g_slotw[tok * 2 + 0];
    float w1 = g_slotw[tok * 2 + 1];
    const float* o0 = g_out2 + (long)(tok * 2 + 0) * HID;
    const float* o1 = g_out2 + (long)(tok * 2 + 1) * HID;
    float* xr = g_x + (long)tok * HID;
    for (int h = threadIdx.x; h < HID; h += blockDim.x)
        xr[h] += w0 * o0[h] + w1 * o1[h];
}

// ---------------------------------------------------------------------------
extern "C" void kernel_launch(void* const* d_in, const int* in_sizes, int n_in,
                              void* d_out, int out_size) {
    const int*   idx  = (const int*)  d_in[0];
    const float* tok  = (const float*)d_in[1];
    const float* pos  = (const float*)d_in[2];
    const float* ln1g = (const float*)d_in[3];
    const float* ln1b = (const float*)d_in[4];
    const float* wqkv = (const float*)d_in[5];
    const float* bqkv = (const float*)d_in[6];
    const float* wo   = (const float*)d_in[7];
    const float* bo   = (const float*)d_in[8];
    const float* ln2g = (const float*)d_in[9];
    const float* ln2b = (const float*)d_in[10];
    const float* rw   = (const float*)d_in[11];
    const float* w1   = (const float*)d_in[12];
    const float* w2   = (const float*)d_in[13];
    const float* lnfg = (const float*)d_in[14];
    const float* lnfb = (const float*)d_in[15];
    float* out = (float*)d_out;

    cudaFuncSetAttribute(bfgemm_k, cudaFuncAttributeMaxDynamicSharedMemorySize, SM_TOT);

    void *px_, *pln_, *pqkv_, *pattn_, *phid_, *pout2_, *pel_, *pec_;
    cudaGetSymbolAddress(&px_,    g_x);
    cudaGetSymbolAddress(&pln_,   g_ln);
    cudaGetSymbolAddress(&pqkv_,  g_qkv);
    cudaGetSymbolAddress(&pattn_, g_attn);
    cudaGetSymbolAddress(&phid_,  g_hid);
    cudaGetSymbolAddress(&pout2_, g_out2);
    cudaGetSymbolAddress(&pel_,   g_elist);
    cudaGetSymbolAddress(&pec_,   g_ecnt);
    float* px    = (float*)px_;
    float* pln   = (float*)pln_;
    float* pqkv  = (float*)pqkv_;
    float* pattn = (float*)pattn_;
    float* phid  = (float*)phid_;
    float* pout2 = (float*)pout2_;
    const int* pel = (const int*)pel_;
    const int* pec = (const int*)pec_;

    embed_k<<<SQ, 256>>>(idx, tok, pos);

    for (int l = 0; l < NLAY; l++) {
        ln_k<<<SQ, 256>>>(px, pln, ln1g + l * HID, ln1b + l * HID);
        // qkv = x_ln @ wqkv.T + bqkv  (M=2048, N=3072, K=1024; wqkv [N,K] -> transB=1)
        bfgemm_k<<<dim3(24, 16, 1), 256, SM_TOT>>>(
            pln, HID,
            wqkv + (long)l * 3 * HID * HID, HID, 1, 0,
            bqkv + (long)l * 3 * HID,
            pqkv, 3 * HID,
            SQ, 3 * HID, HID,
            0, 0, 0, nullptr, nullptr);
        attn_k<<<dim3(SQ / 64, NHEAD), 128>>>();
        // x += attn @ wo.T + bo  (M=2048, N=1024, K=1024)
        bfgemm_k<<<dim3(8, 16, 1), 256, SM_TOT>>>(
            pattn, HID,
            wo + (long)l * HID * HID, HID, 1, 0,
            bo + (long)l * HID,
            px, HID,
            SQ, HID, HID,
            1, 0, 0, nullptr, nullptr);
        ln_k<<<SQ, 256>>>(px, pln, ln2g + l * HID, ln2b + l * HID);
        zero_cnt_k<<<1, 32>>>();
        router_k<<<SQ, 128>>>(rw + (long)l * NEXP * HID);
        // hid[slot] = gelu(x_ln[token] @ w1[e])  (w1 [K,N] -> transB=0)
        bfgemm_k<<<dim3(FFD / 128, 16, NEXP), 256, SM_TOT>>>(
            pln, HID,
            w1 + (long)l * NEXP * HID * FFD, FFD, 0, (long)HID * FFD,
            nullptr,
            phid, FFD,
            SQ, FFD, HID,
            0, 1, 1, pel, pec);
        // out2[slot] = hid[slot] @ w2[e]  (w2 [K,N] -> transB=0)
        bfgemm_k<<<dim3(HID / 128, 16, NEXP), 256, SM_TOT>>>(
            phid, FFD,
            w2 + (long)l * NEXP * FFD * HID, HID, 0, (long)FFD * HID,
            nullptr,
            pout2, HID,
            SQ, HID, FFD,
            0, 0, 2, pel, pec);
        combine_k<<<SQ, 256>>>();
    }

    ln_k<<<SQ, 256>>>(px, pln, lnfg, lnfb);
    // logits = LN(x) @ tok_emb.T  (M=2048, N=32000, K=1024; tok [N,K] -> transB=1)
    bfgemm_k<<<dim3(VOC / 128, 16, 1), 256, SM_TOT>>>(
        pln, HID,
        tok, HID, 1, 0,
        nullptr,
        out, VOC,
        SQ, VOC, HID,
        0, 0, 0, nullptr, nullptr);
}

// round 11
// speedup vs baseline: 1.6290x; 1.1003x over previous
#include <cuda_runtime.h>
#include <cuda_bf16.h>
#include <math.h>
#include <stdint.h>

// ---- model dims ----
#define SQ   2048
#define HID  1024
#define NHEAD 16
#define HD   64
#define FFD  4096
#define NEXP 8
#define TOPK 2
#define VOC  32000
#define NLAY 2

typedef unsigned long long u64;

// ---------------- f32x2 helpers ----------------
__device__ __forceinline__ u64 pk2(float lo, float hi) {
    u64 r; asm("mov.b64 %0, {%1,%2};" : "=l"(r) : "f"(lo), "f"(hi)); return r;
}
__device__ __forceinline__ void upk2(u64 v, float& lo, float& hi) {
    asm("mov.b64 {%0,%1}, %2;" : "=f"(lo), "=f"(hi) : "l"(v));
}
__device__ __forceinline__ u64 ffma2(u64 a, u64 b, u64 c) {
    u64 d; asm("fma.rn.f32x2 %0, %1, %2, %3;" : "=l"(d) : "l"(a), "l"(b), "l"(c)); return d;
}
__device__ __forceinline__ u64 fmul2(u64 a, u64 b) {
    u64 d; asm("mul.rn.f32x2 %0, %1, %2;" : "=l"(d) : "l"(a), "l"(b)); return d;
}

// ---------------- bf16 split / mma ----------------
__device__ __forceinline__ void bfsplit2(float x0, float x1, uint32_t& h, uint32_t& l) {
    __nv_bfloat16 h0 = __float2bfloat16(x0);
    __nv_bfloat16 h1 = __float2bfloat16(x1);
    float r0 = x0 - __bfloat162float(h0);
    float r1 = x1 - __bfloat162float(h1);
    __nv_bfloat16 l0 = __float2bfloat16(r0);
    __nv_bfloat16 l1 = __float2bfloat16(r1);
    h = ((uint32_t)__bfloat16_as_ushort(h1) << 16) | (uint32_t)__bfloat16_as_ushort(h0);
    l = ((uint32_t)__bfloat16_as_ushort(l1) << 16) | (uint32_t)__bfloat16_as_ushort(l0);
}
__device__ __forceinline__ void mma_bf16(float& d0, float& d1, float& d2, float& d3,
                                         uint32_t a0, uint32_t a1, uint32_t a2, uint32_t a3,
                                         uint32_t b0, uint32_t b1) {
    asm volatile(
        "mma.sync.aligned.m16n8k16.row.col.f32.bf16.bf16.f32 "
        "{%0,%1,%2,%3},{%4,%5,%6,%7},{%8,%9},{%0,%1,%2,%3};"
        : "+f"(d0), "+f"(d1), "+f"(d2), "+f"(d3)
        : "r"(a0), "r"(a1), "r"(a2), "r"(a3), "r"(b0), "r"(b1));
}

// ---------------- cp.async ----------------
__device__ __forceinline__ uint32_t s2u(const void* p) {
    uint32_t a;
    asm("{ .reg .u64 t; cvta.to.shared.u64 t, %1; cvt.u32.u64 %0, t; }" : "=r"(a) : "l"(p));
    return a;
}
__device__ __forceinline__ void cpa16(uint32_t dst, const void* src) {
    asm volatile("cp.async.cg.shared.global [%0], [%1], 16;" :: "r"(dst), "l"(src));
}
#define CP_COMMIT() asm volatile("cp.async.commit_group;" ::: "memory")
#define CP_WAIT(n)  asm volatile("cp.async.wait_group %0;" :: "n"(n) : "memory")

// ---- scratch (device globals) ----
__device__ float g_x   [SQ * HID];
__device__ float g_ln  [SQ * HID];
__device__ float g_qkv [SQ * 3 * HID];
__device__ float g_out2[SQ * TOPK * HID];
__device__ float g_slotw[SQ * TOPK];
__device__ int   g_elist[NEXP * SQ];
__device__ int   g_ecnt [NEXP];

// pre-split bf16x2 planes (hi/lo), all K-major [rows][K/2] u32
__device__ uint32_t g_wqkvh[NLAY * 3 * HID * HID / 2], g_wqkvl[NLAY * 3 * HID * HID / 2];
__device__ uint32_t g_woh  [NLAY * HID * HID / 2],     g_wol  [NLAY * HID * HID / 2];
__device__ uint32_t g_w1h  [NLAY * NEXP * FFD * HID / 2], g_w1l[NLAY * NEXP * FFD * HID / 2];
__device__ uint32_t g_w2h  [NLAY * NEXP * HID * FFD / 2], g_w2l[NLAY * NEXP * HID * FFD / 2];
__device__ uint32_t g_tokh [VOC * HID / 2],            g_tokl [VOC * HID / 2];
__device__ uint32_t g_lnh  [SQ * HID / 2],             g_lnl  [SQ * HID / 2];
__device__ uint32_t g_attnh[SQ * HID / 2],             g_attnl[SQ * HID / 2];
__device__ uint32_t g_hidh [SQ * TOPK * FFD / 2],      g_hidl [SQ * TOPK * FFD / 2];

// ---------------------------------------------------------------------------
__global__ void embed_k(const int* __restrict__ idx,
                        const float* __restrict__ tok,
                        const float* __restrict__ pos) {
    int s = blockIdx.x;
    int row = idx[s];
    for (int h = threadIdx.x; h < HID; h += blockDim.x)
        g_x[s * HID + h] = tok[(long)row * HID + h] + pos[(long)s * HID + h];
}

// ---------------------------------------------------------------------------
// pack K-major f32 [R,K] -> bf16x2 hi/lo planes [R,K/2]
__global__ void conv_pack_k(const float* __restrict__ src,
                            uint32_t* __restrict__ dh, uint32_t* __restrict__ dl,
                            long total) {
    long i = (long)blockIdx.x * 256 + threadIdx.x;
    if (i >= total) return;
    float2 v = ((const float2*)src)[i];
    uint32_t h, l;
    bfsplit2(v.x, v.y, h, l);
    dh[i] = h; dl[i] = l;
}

// transpose+pack: src f32 [Kd,Nd] per matrix -> planes [Nd,Kd/2]
__global__ void conv_tr_k(const float* __restrict__ src,
                          uint32_t* __restrict__ dh, uint32_t* __restrict__ dl,
                          int Kd, int Nd, long msi, long mso) {
    __shared__ float sm[64][33];
    int z = blockIdx.z;
    int k0 = blockIdx.x * 64, n0 = blockIdx.y * 32;
    int t = threadIdx.x;
    const float* S = src + (long)z * msi;
    int tk = t >> 5, tn = t & 31;
    #pragma unroll
    for (int i = 0; i < 8; i++)
        sm[tk + 8 * i][tn] = S[(long)(k0 + tk + 8 * i) * Nd + n0 + tn];
    __syncthreads();
    int kk = t & 31, nl = t >> 5;
    #pragma unroll
    for (int j = 0; j < 4; j++) {
        int n = nl + 8 * j;
        uint32_t h, l;
        bfsplit2(sm[2 * kk][n], sm[2 * kk + 1][n], h, l);
        long o = (long)z * mso + (long)(n0 + n) * (Kd >> 1) + (k0 >> 1) + kk;
        dh[o] = h; dl[o] = l;
    }
}

// ---------------------------------------------------------------------------
// LayerNorm: 256 threads, 4 elems each; writes f32 + split planes.
__global__ void ln_k(const float* __restrict__ in, float* __restrict__ outf,
                     uint32_t* __restrict__ oh, uint32_t* __restrict__ ol,
                     const float* __restrict__ g, const float* __restrict__ b) {
    int s = blockIdx.x, t = threadIdx.x;
    __shared__ float red[256];
    float4 v = ((const float4*)(in + (long)s * HID))[t];
    red[t] = v.x + v.y + v.z + v.w;
    __syncthreads();
    for (int o = 128; o > 0; o >>= 1) { if (t < o) red[t] += red[t + o]; __syncthreads(); }
    float mu = red[0] * (1.0f / HID);
    __syncthreads();
    float dx = v.x - mu, dy = v.y - mu, dz = v.z - mu, dw = v.w - mu;
    red[t] = dx * dx + dy * dy + dz * dz + dw * dw;
    __syncthreads();
    for (int o = 128; o > 0; o >>= 1) { if (t < o) red[t] += red[t + o]; __syncthreads(); }
    float inv = rsqrtf(red[0] * (1.0f / HID) + 1e-5f);
    float4 gg = ((const float4*)g)[t], bb = ((const float4*)b)[t];
    float4 o4;
    o4.x = dx * inv * gg.x + bb.x;
    o4.y = dy * inv * gg.y + bb.y;
    o4.z = dz * inv * gg.z + bb.z;
    o4.w = dw * inv * gg.w + bb.w;
    ((float4*)(outf + (long)s * HID))[t] = o4;
    uint32_t h0, l0, h1, l1;
    bfsplit2(o4.x, o4.y, h0, l0);
    bfsplit2(o4.z, o4.w, h1, l1);
    long p = (long)s * 512 + 2 * t;
    oh[p] = h0; oh[p + 1] = h1; ol[p] = l0; ol[p + 1] = l1;
}

// ---------------------------------------------------------------------------
// 3-term bf16 GEMM (hh + hl + lh), operands pre-split planes, cp.async loads.
// 128x128x32 tile, 256 threads (8 warps 2x4), warp tile 64x32, double-buffered.
// B always K-major planes [N][K/2]. Output: f32 C (bias/gelu/accum) or planes Chi/Clo.
#define ASTRIDE 20
#define PLANE   (128 * ASTRIDE)
#define BUFU32  (4 * PLANE)
#define SM_TOT  (2 * BUFU32 * 4)   // 81920 B

__global__ void __launch_bounds__(256, 2) bfgemm_k(
        const uint32_t* __restrict__ Ah, const uint32_t* __restrict__ Al, int lda2,
        const uint32_t* __restrict__ Bh_, const uint32_t* __restrict__ Bl_, long strideB,
        const float* __restrict__ bias,
        float* __restrict__ C, int ldc,
        uint32_t* __restrict__ Chi, uint32_t* __restrict__ Clo, int ldc2,
        int M, int N, int K,
        int accum, int gelu, int row_mode,
        const int* __restrict__ elist, const int* __restrict__ ecnt) {
    extern __shared__ uint32_t smem[];
    uint32_t sb = s2u(smem);

    int e = blockIdx.z;
    long eoff = (long)e * strideB;
    int Me = M;
    const int* list = nullptr;
    if (row_mode) { Me = ecnt[e]; list = elist + e * SQ; }
    int m0 = blockIdx.y * 128;
    if (m0 >= Me) return;
    int n0 = blockIdx.x * 128;

    int t = threadIdx.x;
    int lane = t & 31, wid = t >> 5;
    int warp_m = wid >> 2, warp_n = wid & 3;
    int g = lane >> 2, t4 = lane & 3;

    // loader: row r = t&127 for both A and B; seg = t>>7 covers 8 u32 halves
    int am = t & 127, seg = t >> 7;
    int lrow = m0 + am;
    const uint32_t* Arh = nullptr;
    const uint32_t* Arl = nullptr;
    if (lrow < Me) {
        long gr;
        if (row_mode == 0) gr = lrow;
        else { int slot = list[lrow]; gr = (row_mode == 1) ? (slot >> 1) : slot; }
        Arh = Ah + gr * (long)lda2;
        Arl = Al + gr * (long)lda2;
    }
    int ldb2 = K >> 1;
    const uint32_t* Brh = Bh_ + eoff + (long)(n0 + am) * ldb2;
    const uint32_t* Brl = Bl_ + eoff + (long)(n0 + am) * ldb2;

    int nch = K / 32;

    auto issue = [&](int c, int b) {
        int off = c * 16 + seg * 8;
        uint32_t base = sb + (uint32_t)(b * BUFU32) * 4u;
        uint32_t da = base + (uint32_t)(am * ASTRIDE + seg * 8) * 4u;
        if (Arh) {
            cpa16(da,                    Arh + off);
            cpa16(da + 16,               Arh + off + 4);
            cpa16(da + PLANE * 4,        Arl + off);
            cpa16(da + PLANE * 4 + 16,   Arl + off + 4);
        }
        uint32_t db = base + (uint32_t)(2 * PLANE + am * ASTRIDE + seg * 8) * 4u;
        cpa16(db,                    Brh + off);
        cpa16(db + 16,               Brh + off + 4);
        cpa16(db + PLANE * 4,        Brl + off);
        cpa16(db + PLANE * 4 + 16,   Brl + off + 4);
        CP_COMMIT();
    };

    float acc[4][4][4];
    #pragma unroll
    for (int i = 0; i < 4; i++)
        #pragma unroll
        for (int j = 0; j < 4; j++)
            #pragma unroll
            for (int c = 0; c < 4; c++) acc[i][j][c] = 0.f;

    issue(0, 0);
    for (int c = 0; c < nch; c++) {
        int b = c & 1;
        if (c + 1 < nch) { issue(c + 1, b ^ 1); CP_WAIT(1); }
        else             { CP_WAIT(0); }
        __syncthreads();

        const uint32_t* base = smem + b * BUFU32;
        const uint32_t* pah = base + (warp_m * 64) * ASTRIDE;
        const uint32_t* pal = base + PLANE + (warp_m * 64) * ASTRIDE;
        const uint32_t* pbh = base + 2 * PLANE + (warp_n * 32) * ASTRIDE;
        const uint32_t* pbl = base + 3 * PLANE + (warp_n * 32) * ASTRIDE;

        #pragma unroll
        for (int ks = 0; ks < 2; ks++) {
            int kc = ks * 8;
            uint32_t afh[4][4], afl[4][4], bfh[4][2], bfl[4][2];
            #pragma unroll
            for (int mt = 0; mt < 4; mt++) {
                int r0 = (mt * 16 + g) * ASTRIDE + kc + t4;
                int r1 = (mt * 16 + g + 8) * ASTRIDE + kc + t4;
                afh[mt][0] = pah[r0]; afh[mt][1] = pah[r1];
                afh[mt][2] = pah[r0 + 4]; afh[mt][3] = pah[r1 + 4];
                afl[mt][0] = pal[r0]; afl[mt][1] = pal[r1];
                afl[mt][2] = pal[r0 + 4]; afl[mt][3] = pal[r1 + 4];
            }
            #pragma unroll
            for (int nt = 0; nt < 4; nt++) {
                int r = (nt * 8 + g) * ASTRIDE + kc + t4;
                bfh[nt][0] = pbh[r]; bfh[nt][1] = pbh[r + 4];
                bfl[nt][0] = pbl[r]; bfl[nt][1] = pbl[r + 4];
            }
            #pragma unroll
            for (int mt = 0; mt < 4; mt++)
                #pragma unroll
                for (int nt = 0; nt < 4; nt++) {
                    float* a = acc[mt][nt];
                    mma_bf16(a[0], a[1], a[2], a[3],
                             afh[mt][0], afh[mt][1], afh[mt][2], afh[mt][3],
                             bfh[nt][0], bfh[nt][1]);
                    mma_bf16(a[0], a[1], a[2], a[3],
                             afh[mt][0], afh[mt][1], afh[mt][2], afh[mt][3],
                             bfl[nt][0], bfl[nt][1]);
                    mma_bf16(a[0], a[1], a[2], a[3],
                             afl[mt][0], afl[mt][1], afl[mt][2], afl[mt][3],
                             bfh[nt][0], bfh[nt][1]);
                }
        }
        __syncthreads();
    }

    // ---- epilogue ----
    #pragma unroll
    for (int mt = 0; mt < 4; mt++) {
        int rbase = warp_m * 64 + mt * 16 + g;
        #pragma unroll
        for (int p = 0; p < 2; p++) {
            int lr = m0 + rbase + 8 * p;
            if (lr >= Me) continue;
            long crow = row_mode ? (long)list[lr] : (long)lr;
            if (Chi) {
                long ob = crow * (long)ldc2 + ((n0 + warp_n * 32) >> 1);
                #pragma unroll
                for (int nt = 0; nt < 4; nt++) {
                    int col = nt * 8 + 2 * t4;
                    float v0 = acc[mt][nt][2 * p];
                    float v1 = acc[mt][nt][2 * p + 1];
                    if (gelu) { v0 = v0 * normcdff(v0); v1 = v1 * normcdff(v1); }
                    uint32_t h, l;
                    bfsplit2(v0, v1, h, l);
                    Chi[ob + (col >> 1)] = h;
                    Clo[ob + (col >> 1)] = l;
                }
            } else {
                float* cp = C + crow * (long)ldc + n0 + warp_n * 32;
                const float* bp = bias ? bias + n0 + warp_n * 32 : nullptr;
                #pragma unroll
                for (int nt = 0; nt < 4; nt++) {
                    int col = nt * 8 + 2 * t4;
                    float v0 = acc[mt][nt][2 * p];
                    float v1 = acc[mt][nt][2 * p + 1];
                    if (bp) { v0 += bp[col]; v1 += bp[col + 1]; }
                    if (gelu) { v0 = v0 * normcdff(v0); v1 = v1 * normcdff(v1); }
                    if (accum) { v0 += cp[col]; v1 += cp[col + 1]; }
                    *(float2*)&cp[col] = make_float2(v0, v1);
                }
            }
        }
    }
}

// ---------------------------------------------------------------------------
// Causal flash attention: 256 threads = 64 queries x 4 quarter-threads (16 dims),
// batch-8 online softmax, f32x2 math; writes split planes for the Wo GEMM.
__global__ void attn_k() {
    int h  = blockIdx.y;
    int q0 = blockIdx.x * 64;
    int t  = threadIdx.x;
    int ql = t >> 2, q4 = t & 3;
    int q  = q0 + ql;

    u64 qv2[8];
    {
        const float* qptr = &g_qkv[(long)q * 3072 + h * 64 + q4 * 16];
        #pragma unroll
        for (int i = 0; i < 4; i++) {
            ulonglong2 v = *(const ulonglong2*)&qptr[i * 4];
            qv2[2 * i] = v.x; qv2[2 * i + 1] = v.y;
        }
    }

    float m = -1e30f, l = 0.f;
    u64 acc2[8];
    #pragma unroll
    for (int i = 0; i < 8; i++) acc2[i] = 0ULL;

    __shared__ float Ks[64][64];
    __shared__ float Vs[64][64];

    for (int kt = 0; kt <= q0 + 63; kt += 64) {
        #pragma unroll
        for (int i = t * 4; i < 64 * 64; i += 256 * 4) {
            int kk = i >> 6, d = i & 63;
            *(float4*)&Ks[kk][d] = *(const float4*)&g_qkv[(long)(kt + kk) * 3072 + 1024 + h * 64 + d];
            *(float4*)&Vs[kk][d] = *(const float4*)&g_qkv[(long)(kt + kk) * 3072 + 2048 + h * 64 + d];
        }
        __syncthreads();

        int kmax = q - kt + 1;
        if (kmax > 64) kmax = 64;

        for (int kb = 0; kb < 64; kb += 8) {
            float s[8];
            #pragma unroll
            for (int j = 0; j < 8; j++) {
                const u64* K2 = (const u64*)&Ks[kb + j][q4 * 16];
                u64 p2 = 0ULL;
                #pragma unroll
                for (int i = 0; i < 8; i++) p2 = ffma2(qv2[i], K2[i], p2);
                float lo, hi;
                upk2(p2, lo, hi);
                float p = lo + hi;
                p += __shfl_xor_sync(0xffffffffu, p, 1);
                p += __shfl_xor_sync(0xffffffffu, p, 2);
                s[j] = p * 0.125f;
            }

            int c = kmax - kb; if (c > 8) c = 8;
            if (c <= 0) continue;

            float bm = s[0];
            #pragma unroll
            for (int j = 1; j < 8; j++) if (j < c) bm = fmaxf(bm, s[j]);
            float mn = fmaxf(m, bm);
            float cor = __expf(m - mn);
            m = mn;
            l *= cor;
            u64 cor2 = pk2(cor, cor);
            #pragma unroll
            for (int i = 0; i < 8; i++) acc2[i] = fmul2(acc2[i], cor2);

            #pragma unroll
            for (int j = 0; j < 8; j++) {
                if (j >= c) break;
                float pe = __expf(s[j] - mn);
                l += pe;
                u64 pe2 = pk2(pe, pe);
                const u64* V2 = (const u64*)&Vs[kb + j][q4 * 16];
                #pragma unroll
                for (int i = 0; i < 8; i++) acc2[i] = ffma2(V2[i], pe2, acc2[i]);
            }
        }
        __syncthreads();
    }

    float inv = 1.f / l;
    long pidx = (long)q * 512 + h * 32 + q4 * 8;
    #pragma unroll
    for (int i = 0; i < 8; i++) {
        float lo, hi;
        upk2(acc2[i], lo, hi);
        uint32_t hh, ll;
        bfsplit2(lo * inv, hi * inv, hh, ll);
        g_attnh[pidx + i] = hh;
        g_attnl[pidx + i] = ll;
    }
}

// ---------------------------------------------------------------------------
__global__ void zero_cnt_k() { if (threadIdx.x < NEXP) g_ecnt[threadIdx.x] = 0; }

__global__ void router_k(const float* __restrict__ rw) {
    int tok = blockIdx.x, t = threadIdx.x;   // 128 threads
    __shared__ float sm[NEXP][128];
    __shared__ float logits[NEXP];
    const float* xr = g_ln + (long)tok * HID;

    for (int e = 0; e < NEXP; e++) {
        float s = 0.f;
        for (int j = t; j < HID; j += 128) s += xr[j] * rw[e * HID + j];
        sm[e][t] = s;
    }
    __syncthreads();
    if (t < NEXP) {
        float s = 0.f;
        for (int j = 0; j < 128; j++) s += sm[t][j];
        logits[t] = s;
    }
    __syncthreads();
    if (t == 0) {
        float mx = logits[0];
        for (int e = 1; e < NEXP; e++) mx = fmaxf(mx, logits[e]);
        float p[NEXP], den = 0.f;
        for (int e = 0; e < NEXP; e++) { p[e] = expf(logits[e] - mx); den += p[e]; }
        float idn = 1.f / den;
        for (int e = 0; e < NEXP; e++) p[e] *= idn;
        int i1 = 0;
        for (int e = 1; e < NEXP; e++) if (p[e] > p[i1]) i1 = e;
        int i2 = -1;
        for (int e = 0; e < NEXP; e++) {
            if (e == i1) continue;
            if (i2 < 0 || p[e] > p[i2]) i2 = e;
        }
        g_slotw[tok * 2 + 0] = p[i1];
        g_slotw[tok * 2 + 1] = p[i2];
        int p1 = atomicAdd(&g_ecnt[i1], 1); g_elist[i1 * SQ + p1] = tok * 2 + 0;
        int p2 = atomicAdd(&g_ecnt[i2], 1); g_elist[i2 * SQ + p2] = tok * 2 + 1;
    }
}

// ---------------------------------------------------------------------------
__global__ void combine_k() {
    int tok = blockIdx.x;
    float w0 = g_slotw[tok * 2 + 0];
    float w1 = g_slotw[tok * 2 + 1];
    const float* o0 = g_out2 + (long)(tok * 2 + 0) * HID;
    const float* o1 = g_out2 + (long)(tok * 2 + 1) * HID;
    float* xr = g_x + (long)tok * HID;
    for (int h = threadIdx.x; h < HID; h += blockDim.x)
        xr[h] += w0 * o0[h] + w1 * o1[h];
}

// ---------------------------------------------------------------------------
extern "C" void kernel_launch(void* const* d_in, const int* in_sizes, int n_in,
                              void* d_out, int out_size) {
    const int*   idx  = (const int*)  d_in[0];
    const float* tok  = (const float*)d_in[1];
    const float* pos  = (const float*)d_in[2];
    const float* ln1g = (const float*)d_in[3];
    const float* ln1b = (const float*)d_in[4];
    const float* wqkv = (const float*)d_in[5];
    const float* bqkv = (const float*)d_in[6];
    const float* wo   = (const float*)d_in[7];
    const float* bo   = (const float*)d_in[8];
    const float* ln2g = (const float*)d_in[9];
    const float* ln2b = (const float*)d_in[10];
    const float* rw   = (const float*)d_in[11];
    const float* w1   = (const float*)d_in[12];
    const float* w2   = (const float*)d_in[13];
    const float* lnfg = (const float*)d_in[14];
    const float* lnfb = (const float*)d_in[15];
    float* out = (float*)d_out;

    cudaFuncSetAttribute(bfgemm_k, cudaFuncAttributeMaxDynamicSharedMemorySize, SM_TOT);

    // symbol addresses
    void* p_;
    #define SYM(var, sym) cudaGetSymbolAddress(&p_, sym); auto var = p_
    SYM(px_, g_x);        float* px = (float*)px_;
    SYM(pln_, g_ln);      float* pln = (float*)pln_;
    SYM(pqkv_, g_qkv);    float* pqkv = (float*)pqkv_;
    SYM(pout2_, g_out2);  float* pout2 = (float*)pout2_;
    SYM(pel_, g_elist);   const int* pel = (const int*)pel_;
    SYM(pec_, g_ecnt);    const int* pec = (const int*)pec_;
    SYM(pwqkvh_, g_wqkvh); uint32_t* pwqkvh = (uint32_t*)pwqkvh_;
    SYM(pwqkvl_, g_wqkvl); uint32_t* pwqkvl = (uint32_t*)pwqkvl_;
    SYM(pwoh_, g_woh);     uint32_t* pwoh = (uint32_t*)pwoh_;
    SYM(pwol_, g_wol);     uint32_t* pwol = (uint32_t*)pwol_;
    SYM(pw1h_, g_w1h);     uint32_t* pw1h = (uint32_t*)pw1h_;
    SYM(pw1l_, g_w1l);     uint32_t* pw1l = (uint32_t*)pw1l_;
    SYM(pw2h_, g_w2h);     uint32_t* pw2h = (uint32_t*)pw2h_;
    SYM(pw2l_, g_w2l);     uint32_t* pw2l = (uint32_t*)pw2l_;
    SYM(ptokh_, g_tokh);   uint32_t* ptokh = (uint32_t*)ptokh_;
    SYM(ptokl_, g_tokl);   uint32_t* ptokl = (uint32_t*)ptokl_;
    SYM(plnh_, g_lnh);     uint32_t* plnh = (uint32_t*)plnh_;
    SYM(plnl_, g_lnl);     uint32_t* plnl = (uint32_t*)plnl_;
    SYM(pattnh_, g_attnh); uint32_t* pattnh = (uint32_t*)pattnh_;
    SYM(pattnl_, g_attnl); uint32_t* pattnl = (uint32_t*)pattnl_;
    SYM(phidh_, g_hidh);   uint32_t* phidh = (uint32_t*)phidh_;
    SYM(phidl_, g_hidl);   uint32_t* phidl = (uint32_t*)phidl_;
    #undef SYM

    // ---- weight conversion (every call; deterministic) ----
    {
        long tq = (long)NLAY * 3 * HID * HID / 2;
        conv_pack_k<<<(unsigned)((tq + 255) / 256), 256>>>(wqkv, pwqkvh, pwqkvl, tq);
        long tw = (long)NLAY * HID * HID / 2;
        conv_pack_k<<<(unsigned)((tw + 255) / 256), 256>>>(wo, pwoh, pwol, tw);
        long tt = (long)VOC * HID / 2;
        conv_pack_k<<<(unsigned)((tt + 255) / 256), 256>>>(tok, ptokh, ptokl, tt);
        // w1: [l,e][H,FF] -> planes [FF][H/2]
        conv_tr_k<<<dim3(HID / 64, FFD / 32, NLAY * NEXP), 256>>>(
            w1, pw1h, pw1l, HID, FFD, (long)HID * FFD, (long)FFD * (HID / 2));
        // w2: [l,e][FF,H] -> planes [H][FF/2]
        conv_tr_k<<<dim3(FFD / 64, HID / 32, NLAY * NEXP), 256>>>(
            w2, pw2h, pw2l, FFD, HID, (long)FFD * HID, (long)HID * (FFD / 2));
    }

    embed_k<<<SQ, 256>>>(idx, tok, pos);

    for (int l = 0; l < NLAY; l++) {
        ln_k<<<SQ, 256>>>(px, pln, plnh, plnl, ln1g + l * HID, ln1b + l * HID);
        // qkv = ln @ wqkv.T + bqkv
        bfgemm_k<<<dim3(24, 16, 1), 256, SM_TOT>>>(
            plnh, plnl, HID / 2,
            pwqkvh + (long)l * 3 * HID * (HID / 2), pwqkvl + (long)l * 3 * HID * (HID / 2), 0,
            bqkv + (long)l * 3 * HID,
            pqkv, 3 * HID, nullptr, nullptr, 0,
            SQ, 3 * HID, HID, 0, 0, 0, nullptr, nullptr);
        attn_k<<<dim3(SQ / 64, NHEAD), 256>>>();
        // x += attn @ wo.T + bo
        bfgemm_k<<<dim3(8, 16, 1), 256, SM_TOT>>>(
            pattnh, pattnl, HID / 2,
            pwoh + (long)l * HID * (HID / 2), pwol + (long)l * HID * (HID / 2), 0,
            bo + (long)l * HID,
            px, HID, nullptr, nullptr, 0,
            SQ, HID, HID, 1, 0, 0, nullptr, nullptr);
        ln_k<<<SQ, 256>>>(px, pln, plnh, plnl, ln2g + l * HID, ln2b + l * HID);
        zero_cnt_k<<<1, 32>>>();
        router_k<<<SQ, 128>>>(rw + (long)l * NEXP * HID);
        // hid[slot] = gelu(ln2[token] @ w1[e])  -> planes
        bfgemm_k<<<dim3(FFD / 128, 16, NEXP), 256, SM_TOT>>>(
            plnh, plnl, HID / 2,
            pw1h + (long)l * NEXP * FFD * (HID / 2), pw1l + (long)l * NEXP * FFD * (HID / 2),
            (long)FFD * (HID / 2),
            nullptr,
            nullptr, 0, phidh, phidl, FFD / 2,
            SQ, FFD, HID, 0, 1, 1, pel, pec);
        // out2[slot] = hid[slot] @ w2[e]
        bfgemm_k<<<dim3(HID / 128, 16, NEXP), 256, SM_TOT>>>(
            phidh, phidl, FFD / 2,
            pw2h + (long)l * NEXP * HID * (FFD / 2), pw2l + (long)l * NEXP * HID * (FFD / 2),
            (long)HID * (FFD / 2),
            nullptr,
            pout2, HID, nullptr, nullptr, 0,
            SQ, HID, FFD, 0, 0, 2, pel, pec);
        combine_k<<<SQ, 256>>>();
    }

    ln_k<<<SQ, 256>>>(px, pln, plnh, plnl, lnfg, lnfb);
    // logits = lnf @ tok.T
    bfgemm_k<<<dim3(VOC / 128, 16, 1), 256, SM_TOT>>>(
        plnh, plnl, HID / 2,
        ptokh, ptokl, 0,
        nullptr,
        out, VOC, nullptr, nullptr, 0,
        SQ, VOC, HID, 0, 0, 0, nullptr, nullptr);
}